// round 13
// baseline (speedup 1.0000x reference)
#include <cuda_runtime.h>
#include <cuda_bf16.h>
#include <cstdint>

// ---------------------------------------------------------------------------
// MultiPathLayer: N=50000 nodes, E=800000 edges, D=128.
// GEMMs via mma.sync bf16 (split-bf16, fp32 accuracy), ldmatrix, cp.async,
// single-B-buffer two-stage loading -> 68KB smem + <=85 regs -> 3 CTAs/SM.
// Smem chain-fusion, fused attention + BN stats + accumulator zeroing.
// Edge phase: single fused launch (node+edge blocks + struct blocks).
// ---------------------------------------------------------------------------

#define NMAX 50000
#define DDIM 128
#define WPAD 136           // padded row length in bf16 elems — LDSM conflict-free
#define WELEMS (128 * WPAD)

__device__ float4 g_b0 [NMAX * 32];   // Un   -> later E0
__device__ float4 g_b1 [NMAX * 32];   // Vn   -> later E1
__device__ float4 g_b2 [NMAX * 32];   // Ue   -> later E2
__device__ float4 g_b3 [NMAX * 32];   // Ve
__device__ float4 g_b4 [NMAX * 32];   // Hagg
__device__ float4 g_b5 [NMAX * 32];   // Einit
__device__ float4 g_b6 [NMAX * 32];   // Pn
__device__ float4 g_b7 [NMAX * 32];   // Pe
__device__ float4 g_b8 [NMAX * 32];   // T
__device__ float4 g_b9 [NMAX * 32];   // Fn
__device__ float4 g_b10[NMAX * 32];   // Fe
__device__ float4 g_b13[NMAX * 32];   // Fs
__device__ float  g_s[NMAX];
__device__ float  g_deg[NMAX];
__device__ float  g_bnsum[DDIM];
__device__ float  g_bnsq[DDIM];

// Pre-converted weights: [weight][hi/lo][n*WPAD + k] (B operand layout [n][k]).
__device__ __align__(16) __nv_bfloat16 g_wt[18][2][WELEMS];

__device__ __forceinline__ float mishf(float x) {
    float e  = __expf(fminf(x, 30.0f));
    float t  = 1.0f + e;
    float t2 = t * t;
    return x * __fdividef(t2 - 1.0f, t2 + 1.0f);
}

__device__ __forceinline__ void red_add_v4(float4* p, float4 v) {
    asm volatile("red.global.add.v4.f32 [%0], {%1,%2,%3,%4};"
                 :: "l"(p), "f"(v.x), "f"(v.y), "f"(v.z), "f"(v.w)
                 : "memory");
}

__device__ __forceinline__ uint32_t smem_u32(const void* p) {
    uint32_t a;
    asm("{ .reg .u64 t; cvta.to.shared.u64 t, %1; cvt.u32.u64 %0, t; }"
        : "=r"(a) : "l"(p));
    return a;
}

__device__ __forceinline__ void mma_bf16(float* c, const uint32_t* a,
                                         const uint32_t* b) {
    asm volatile(
        "mma.sync.aligned.m16n8k16.row.col.f32.bf16.bf16.f32 "
        "{%0,%1,%2,%3}, {%4,%5,%6,%7}, {%8,%9}, {%0,%1,%2,%3};"
        : "+f"(c[0]), "+f"(c[1]), "+f"(c[2]), "+f"(c[3])
        : "r"(a[0]), "r"(a[1]), "r"(a[2]), "r"(a[3]), "r"(b[0]), "r"(b[1]));
}

__device__ __forceinline__ void ldsm4(uint32_t* r, uint32_t addr) {
    asm volatile("ldmatrix.sync.aligned.m8n8.x4.shared.b16 {%0,%1,%2,%3}, [%4];"
        : "=r"(r[0]), "=r"(r[1]), "=r"(r[2]), "=r"(r[3]) : "r"(addr));
}

__device__ __forceinline__ void cp_async16(uint32_t saddr, const void* g) {
    asm volatile("cp.async.cg.shared.global [%0], [%1], 16;"
                 :: "r"(saddr), "l"(g) : "memory");
}

// softmax over 3 logits, weighted sum of 3 features (scalar)
__device__ __forceinline__ float att3(float e0, float e1, float e2,
                                      float f0, float f1, float f2) {
    float m = fmaxf(e0, fmaxf(e1, e2));
    float p0 = __expf(e0 - m), p1 = __expf(e1 - m), p2 = __expf(e2 - m);
    return __fdividef(p0 * f0 + p1 * f1 + p2 * f2, p0 + p1 + p2);
}

// ---------------------------------------------------------------------------
// Weight setup.
// ---------------------------------------------------------------------------
struct WPtrs { const float* p[18]; };

__global__ void setup_weights(WPtrs wp)
{
    int w = blockIdx.x;
    const float* W = wp.p[w];
    __nv_bfloat16* hi = g_wt[w][0];
    __nv_bfloat16* lo = g_wt[w][1];
    for (int it = 0; it < 8; ++it) {
        int idx = blockIdx.y * 2048 + it * 256 + threadIdx.x;
        int k = idx >> 7;
        int n = idx & 127;
        float v = W[idx];
        __nv_bfloat16 h = __float2bfloat16(v);
        __nv_bfloat16 l = __float2bfloat16(v - __bfloat162float(h));
        hi[n * WPAD + k] = h;
        lo[n * WPAD + k] = l;
    }
}

// ---------------------------------------------------------------------------
// Fused edge phase: blocks [0, gNE) do node+edge paths (2 edges/warp),
// blocks [gNE, ...) do struct path (4 edges/warp).
// ---------------------------------------------------------------------------
__global__ void __launch_bounds__(256) edge_fused(
    const int*   __restrict__ ei,
    const int*   __restrict__ bt,
    const float* __restrict__ conv_w,
    const float* __restrict__ conv_b,
    const float* __restrict__ b_el,
    const float* __restrict__ coords,
    const float4* __restrict__ x,
    const float4* __restrict__ Un, const float4* __restrict__ Vn,
    const float4* __restrict__ Ue, const float4* __restrict__ Ve,
    float4* Pn, float4* Pe, float4* T,
    float* s_arr, float* deg_arr, int E, int gNE)
{
    int lane = threadIdx.x & 31;

    if ((int)blockIdx.x < gNE) {
        int base = (blockIdx.x * 8 + (threadIdx.x >> 5)) * 2;
        if (base >= E) return;
        int e1ok = (base + 1 < E);

        int src0 = ei[base];
        int dst0 = ei[E + base];
        int src1 = e1ok ? ei[base + 1]     : src0;
        int dst1 = e1ok ? ei[E + base + 1] : dst0;
        float norm0 = conv_w[bt[base]] + conv_b[0];
        float norm1 = conv_w[bt[e1ok ? base + 1 : base]] + conv_b[0];

        int di0 = dst0 * 32 + lane, si0 = src0 * 32 + lane;
        int di1 = dst1 * 32 + lane, si1 = src1 * 32 + lane;

        float4 un0 = Un[di0];
        float4 vn0 = Vn[si0];
        float4 ue0 = Ue[di0];
        float4 ve0 = Ve[si0];
        float4 un1 = Un[di1];
        float4 vn1 = Vn[si1];
        float4 ue1 = Ue[di1];
        float4 ve1 = Ve[si1];
        float4 b   = ((const float4*)b_el)[lane];

        float4 m;
        m.x = mishf(un0.x + vn0.x); m.y = mishf(un0.y + vn0.y);
        m.z = mishf(un0.z + vn0.z); m.w = mishf(un0.w + vn0.w);
        red_add_v4(&Pn[di0], m);

        m.x = mishf(norm0 * (ue0.x + ve0.x) + b.x);
        m.y = mishf(norm0 * (ue0.y + ve0.y) + b.y);
        m.z = mishf(norm0 * (ue0.z + ve0.z) + b.z);
        m.w = mishf(norm0 * (ue0.w + ve0.w) + b.w);
        red_add_v4(&Pe[di0], m);

        if (e1ok) {
            m.x = mishf(un1.x + vn1.x); m.y = mishf(un1.y + vn1.y);
            m.z = mishf(un1.z + vn1.z); m.w = mishf(un1.w + vn1.w);
            red_add_v4(&Pn[di1], m);

            m.x = mishf(norm1 * (ue1.x + ve1.x) + b.x);
            m.y = mishf(norm1 * (ue1.y + ve1.y) + b.y);
            m.z = mishf(norm1 * (ue1.z + ve1.z) + b.z);
            m.w = mishf(norm1 * (ue1.w + ve1.w) + b.w);
            red_add_v4(&Pe[di1], m);
        }
    } else {
        int bid = blockIdx.x - gNE;
        int base = (bid * 8 + (threadIdx.x >> 5)) * 4;
        if (base >= E) return;
        int cnt = min(4, E - base);

        int src[4], dst[4];
        float d2[4];
        #pragma unroll
        for (int q = 0; q < 4; ++q) {
            int e = base + ((q < cnt) ? q : 0);
            src[q] = ei[e];
            dst[q] = ei[E + e];
        }
        #pragma unroll
        for (int q = 0; q < 4; ++q) {
            float dx = coords[src[q] * 3 + 0] - coords[dst[q] * 3 + 0];
            float dy = coords[src[q] * 3 + 1] - coords[dst[q] * 3 + 1];
            float dz = coords[src[q] * 3 + 2] - coords[dst[q] * 3 + 2];
            d2[q] = dx * dx + dy * dy + dz * dz;
        }
        float4 xs[4];
        #pragma unroll
        for (int q = 0; q < 4; ++q)
            xs[q] = x[src[q] * 32 + lane];

        #pragma unroll
        for (int q = 0; q < 4; ++q) {
            if (q >= cnt) break;
            float4 m = make_float4(d2[q] * xs[q].x, d2[q] * xs[q].y,
                                   d2[q] * xs[q].z, d2[q] * xs[q].w);
            red_add_v4(&T[dst[q] * 32 + lane], m);
            if (lane == 0) {
                atomicAdd(&s_arr[dst[q]], d2[q]);
                atomicAdd(&deg_arr[dst[q]], 1.0f);
            }
        }
    }
}

// ---------------------------------------------------------------------------
// Batched / chain-fused mma.sync GEMM, single B buffer (hi then lo reload).
// smem: A_hi[0,17408) A_lo[17408,34816) B[34816,69632)  => 3 CTAs/SM.
// ---------------------------------------------------------------------------
struct Job {
    const float* A; const float* A2;
    const float* rowScale; const float* bias;
    const float* biasRowScale; const float* Cadd;
    const float* aE1; const float* aE2;
    const float* aF0; const float* aF1; const float* aF2;
    float* C;
    int w1, w2, actMode, convertA, chainOut, attn, bnstat, zeroAcc;
};
struct JobList { Job j[12]; int count; };

__global__ void __launch_bounds__(256, 3) mma_gemm(JobList jl, int n)
{
    extern __shared__ __nv_bfloat16 sm[];
    const int tid  = threadIdx.x;
    const int wid  = tid >> 5;
    const int lane = tid & 31;
    const int tq = lane >> 2;
    const int tr = lane & 3;
    const int warpM = wid >> 2;     // 0..1
    const int warpN = wid & 3;      // 0..3
    const int rowBase = blockIdx.x * 64;

    const uint32_t smBase  = smem_u32(sm);
    const uint32_t aHiAddr = smBase;
    const uint32_t aLoAddr = smBase + 17408;
    const uint32_t bAddr   = smBase + 34816;

    const uint32_t aoff0 = ((warpM * 32 + (lane & 15)) * WPAD + (lane >> 4) * 8) * 2;
    const uint32_t aoff1 = aoff0 + 16 * WPAD * 2;
    const int bRow = warpN * 32 + ((lane >> 4) << 3) + (lane & 7);
    const uint32_t boff0 = (bRow * WPAD + ((lane >> 3) & 1) * 8) * 2;
    const uint32_t boff1 = boff0 + 16 * WPAD * 2;

    for (int ji = 0; ji < jl.count; ++ji) {
        const Job J = jl.j[ji];

        float acc[2][4][4];
        #pragma unroll
        for (int i = 0; i < 2; ++i)
            #pragma unroll
            for (int j = 0; j < 4; ++j)
                #pragma unroll
                for (int q = 0; q < 4; ++q) acc[i][j][q] = 0.0f;

        const int passes = (J.A2 != nullptr) ? 2 : 1;
        for (int p = 0; p < passes; ++p) {
            const float* Ap  = p ? J.A2 : J.A;
            const float* rsp = p ? nullptr : J.rowScale;
            const bool doConv = (p == 1) || (J.convertA != 0);
            const int  w = p ? J.w2 : J.w1;

            __syncthreads();   // previous mainloop / chain writes done

            // --- prefetch B_hi (34816 B) ---
            {
                const char* src = (const char*)g_wt[w][0] + tid * 16;
                uint32_t dst = bAddr + tid * 16;
                #pragma unroll
                for (int it = 0; it < 8; ++it)
                    cp_async16(dst + it * 4096, src + it * 4096);
                if (tid < 128) cp_async16(dst + 8 * 4096, src + 8 * 4096);
                asm volatile("cp.async.commit_group;" ::: "memory");
            }

            // --- A tile: 64x128 -> hi/lo bf16 (overlaps B_hi prefetch) ---
            if (doConv) {
                #pragma unroll
                for (int it = 0; it < 8; ++it) {
                    int idx = tid + (it << 8);
                    int row = idx >> 5;
                    int c4  = idx & 31;
                    int grow = rowBase + row;
                    float4 v = make_float4(0.f, 0.f, 0.f, 0.f);
                    if (grow < n) {
                        int gi = grow * 32 + c4;
                        if (J.attn) {
                            float4 e0 = ((const float4*)Ap)[gi];
                            float4 e1 = ((const float4*)J.aE1)[gi];
                            float4 e2 = ((const float4*)J.aE2)[gi];
                            float4 f0 = ((const float4*)J.aF0)[gi];
                            float4 f1 = ((const float4*)J.aF1)[gi];
                            float4 f2 = ((const float4*)J.aF2)[gi];
                            v.x = att3(e0.x, e1.x, e2.x, f0.x, f1.x, f2.x);
                            v.y = att3(e0.y, e1.y, e2.y, f0.y, f1.y, f2.y);
                            v.z = att3(e0.z, e1.z, e2.z, f0.z, f1.z, f2.z);
                            v.w = att3(e0.w, e1.w, e2.w, f0.w, f1.w, f2.w);
                        } else {
                            v = ((const float4*)Ap)[gi];
                            if (rsp) {
                                float s = __ldg(&rsp[grow]);
                                v.x *= s; v.y *= s; v.z *= s; v.w *= s;
                            }
                        }
                    }
                    __nv_bfloat16 hx = __float2bfloat16(v.x);
                    __nv_bfloat16 hy = __float2bfloat16(v.y);
                    __nv_bfloat16 hz = __float2bfloat16(v.z);
                    __nv_bfloat16 hw = __float2bfloat16(v.w);
                    __nv_bfloat162 h01; h01.x = hx; h01.y = hy;
                    __nv_bfloat162 h23; h23.x = hz; h23.y = hw;
                    __nv_bfloat162 l01, l23;
                    l01.x = __float2bfloat16(v.x - __bfloat162float(hx));
                    l01.y = __float2bfloat16(v.y - __bfloat162float(hy));
                    l23.x = __float2bfloat16(v.z - __bfloat162float(hz));
                    l23.y = __float2bfloat16(v.w - __bfloat162float(hw));
                    int o = row * WPAD + c4 * 4;
                    *(__nv_bfloat162*)&sm[o]            = h01;
                    *(__nv_bfloat162*)&sm[o + 2]        = h23;
                    *(__nv_bfloat162*)&sm[8704 + o]     = l01;
                    *(__nv_bfloat162*)&sm[8704 + o + 2] = l23;
                }
            }
            asm volatile("cp.async.wait_group 0;" ::: "memory");
            __syncthreads();

            // --- split terms using B_hi: hi_a·hi_b, lo_a·hi_b ---
            #pragma unroll
            for (int sel = 0; sel < 2; ++sel) {
                const uint32_t aB = (sel == 1) ? aLoAddr : aHiAddr;
                #pragma unroll
                for (int kk = 0; kk < 8; ++kk) {
                    uint32_t ko = kk * 32;
                    uint32_t a0[4], a1[4], b0[4], b1[4];
                    ldsm4(a0, aB + aoff0 + ko);
                    ldsm4(a1, aB + aoff1 + ko);
                    ldsm4(b0, bAddr + boff0 + ko);
                    ldsm4(b1, bAddr + boff1 + ko);
                    mma_bf16(acc[0][0], a0, &b0[0]);
                    mma_bf16(acc[0][1], a0, &b0[2]);
                    mma_bf16(acc[0][2], a0, &b1[0]);
                    mma_bf16(acc[0][3], a0, &b1[2]);
                    mma_bf16(acc[1][0], a1, &b0[0]);
                    mma_bf16(acc[1][1], a1, &b0[2]);
                    mma_bf16(acc[1][2], a1, &b1[0]);
                    mma_bf16(acc[1][3], a1, &b1[2]);
                }
            }
            __syncthreads();   // all warps done with B_hi

            // --- reload buffer with B_lo ---
            {
                const char* src = (const char*)g_wt[w][1] + tid * 16;
                uint32_t dst = bAddr + tid * 16;
                #pragma unroll
                for (int it = 0; it < 8; ++it)
                    cp_async16(dst + it * 4096, src + it * 4096);
                if (tid < 128) cp_async16(dst + 8 * 4096, src + 8 * 4096);
                asm volatile("cp.async.commit_group;" ::: "memory");
                asm volatile("cp.async.wait_group 0;" ::: "memory");
            }
            __syncthreads();

            // --- split term hi_a·lo_b ---
            #pragma unroll
            for (int kk = 0; kk < 8; ++kk) {
                uint32_t ko = kk * 32;
                uint32_t a0[4], a1[4], b0[4], b1[4];
                ldsm4(a0, aHiAddr + aoff0 + ko);
                ldsm4(a1, aHiAddr + aoff1 + ko);
                ldsm4(b0, bAddr + boff0 + ko);
                ldsm4(b1, bAddr + boff1 + ko);
                mma_bf16(acc[0][0], a0, &b0[0]);
                mma_bf16(acc[0][1], a0, &b0[2]);
                mma_bf16(acc[0][2], a0, &b1[0]);
                mma_bf16(acc[0][3], a0, &b1[2]);
                mma_bf16(acc[1][0], a1, &b0[0]);
                mma_bf16(acc[1][1], a1, &b0[2]);
                mma_bf16(acc[1][2], a1, &b1[0]);
                mma_bf16(acc[1][3], a1, &b1[2]);
            }
        }

        if (J.chainOut) {
            __syncthreads();   // all warps done reading A smem
            #pragma unroll
            for (int mt = 0; mt < 2; ++mt) {
                #pragma unroll
                for (int half = 0; half < 2; ++half) {
                    int rloc = warpM * 32 + mt * 16 + tq + half * 8;
                    #pragma unroll
                    for (int nt = 0; nt < 4; ++nt) {
                        int col = warpN * 32 + nt * 8 + tr * 2;
                        float v0 = acc[mt][nt][half * 2];
                        float v1 = acc[mt][nt][half * 2 + 1];
                        if (J.bias) {
                            v0 += __ldg(&J.bias[col]);
                            v1 += __ldg(&J.bias[col + 1]);
                        }
                        if (J.actMode == 1)      { v0 = mishf(v0); v1 = mishf(v1); }
                        else if (J.actMode == 2) { v0 = mishf(mishf(v0)); v1 = mishf(mishf(v1)); }
                        __nv_bfloat16 h0 = __float2bfloat16(v0);
                        __nv_bfloat16 h1 = __float2bfloat16(v1);
                        __nv_bfloat162 hh; hh.x = h0; hh.y = h1;
                        __nv_bfloat162 ll;
                        ll.x = __float2bfloat16(v0 - __bfloat162float(h0));
                        ll.y = __float2bfloat16(v1 - __bfloat162float(h1));
                        int o = rloc * WPAD + col;
                        *(__nv_bfloat162*)&sm[o]        = hh;
                        *(__nv_bfloat162*)&sm[8704 + o] = ll;
                    }
                }
            }
        } else {
            float* scol = (float*)sm;          // [128] sums, [128] sumsq
            if (J.bnstat) {
                __syncthreads();               // mainloop smem reads done
                if (tid < 256) scol[tid] = 0.0f;
                __syncthreads();
            }
            float cs[8], cq[8];
            #pragma unroll
            for (int q = 0; q < 8; ++q) { cs[q] = 0.f; cq[q] = 0.f; }

            #pragma unroll
            for (int mt = 0; mt < 2; ++mt) {
                #pragma unroll
                for (int half = 0; half < 2; ++half) {
                    int grow = rowBase + warpM * 32 + mt * 16 + tq + half * 8;
                    if (grow >= n) continue;
                    float brs = J.biasRowScale ? __ldg(&J.biasRowScale[grow]) : 1.0f;
                    #pragma unroll
                    for (int nt = 0; nt < 4; ++nt) {
                        int col = warpN * 32 + nt * 8 + tr * 2;
                        float v0 = acc[mt][nt][half * 2];
                        float v1 = acc[mt][nt][half * 2 + 1];
                        if (J.bias) {
                            v0 += __ldg(&J.bias[col])     * brs;
                            v1 += __ldg(&J.bias[col + 1]) * brs;
                        }
                        if (J.Cadd) {
                            float2 ca = *(const float2*)&J.Cadd[grow * 128 + col];
                            v0 += ca.x; v1 += ca.y;
                        }
                        if (J.actMode == 1)      { v0 = mishf(v0); v1 = mishf(v1); }
                        else if (J.actMode == 2) { v0 = mishf(mishf(v0)); v1 = mishf(mishf(v1)); }
                        *(float2*)&J.C[grow * 128 + col] = make_float2(v0, v1);
                        if (J.bnstat) {
                            cs[nt * 2]     += v0; cq[nt * 2]     += v0 * v0;
                            cs[nt * 2 + 1] += v1; cq[nt * 2 + 1] += v1 * v1;
                        }
                    }
                }
            }
            if (J.bnstat) {
                #pragma unroll
                for (int nt = 0; nt < 4; ++nt) {
                    int col = warpN * 32 + nt * 8 + tr * 2;
                    atomicAdd(&scol[col],           cs[nt * 2]);
                    atomicAdd(&scol[col + 1],       cs[nt * 2 + 1]);
                    atomicAdd(&scol[128 + col],     cq[nt * 2]);
                    atomicAdd(&scol[128 + col + 1], cq[nt * 2 + 1]);
                }
                __syncthreads();
                if (tid < 128) {
                    atomicAdd(&g_bnsum[tid], scol[tid]);
                    atomicAdd(&g_bnsq[tid],  scol[128 + tid]);
                }
            }
            if (J.zeroAcc) {
                float4 z = make_float4(0.f, 0.f, 0.f, 0.f);
                #pragma unroll
                for (int it = 0; it < 8; ++it) {
                    int idx = tid + (it << 8);
                    int row = idx >> 5;
                    int c   = idx & 31;
                    int grow = rowBase + row;
                    if (grow < n) {
                        g_b6[grow * 32 + c] = z;
                        g_b7[grow * 32 + c] = z;
                        g_b8[grow * 32 + c] = z;
                    }
                }
                if (tid < 64) {
                    int grow = rowBase + tid;
                    if (grow < n) { g_s[grow] = 0.f; g_deg[grow] = 0.f; }
                }
            }
        }
    }
}

// ---------------------------------------------------------------------------
__global__ void final_kernel(const float* __restrict__ H,
                             const float* __restrict__ sum,
                             const float* __restrict__ sq,
                             const float* __restrict__ gamma,
                             const float* __restrict__ beta,
                             float* __restrict__ out, int n)
{
    int i = blockIdx.x * blockDim.x + threadIdx.x;
    if (i >= n * 128) return;
    int d = i & 127;
    float invn = 1.0f / (float)n;
    float mean = sum[d] * invn;
    float var  = sq[d] * invn - mean * mean;
    float v = (H[i] - mean) * rsqrtf(var + 1e-5f) * gamma[d] + beta[d];
    out[i] = mishf(v);
}

// ---------------------------------------------------------------------------
// Host launch
// ---------------------------------------------------------------------------
static float* symaddr(const void* sym) {
    void* p = nullptr;
    cudaGetSymbolAddress(&p, sym);
    return (float*)p;
}

#define GEMM_SMEM 69632

static Job mkjob(const float* A, int w1, float* C, int act,
                 const float* bias = nullptr, int convertA = 1,
                 const float* A2 = nullptr, int w2 = -1,
                 const float* rowScale = nullptr,
                 const float* brs = nullptr, const float* Cadd = nullptr,
                 int chainOut = 0)
{
    Job j;
    j.A = A; j.A2 = A2; j.rowScale = rowScale; j.bias = bias;
    j.biasRowScale = brs; j.Cadd = Cadd; j.C = C;
    j.aE1 = nullptr; j.aE2 = nullptr;
    j.aF0 = nullptr; j.aF1 = nullptr; j.aF2 = nullptr;
    j.w1 = w1; j.w2 = w2; j.actMode = act; j.convertA = convertA;
    j.chainOut = chainOut; j.attn = 0; j.bnstat = 0; j.zeroAcc = 0;
    return j;
}

extern "C" void kernel_launch(void* const* d_in, const int* in_sizes, int n_in,
                              void* d_out, int out_size)
{
    const float* x       = (const float*)d_in[0];
    const float* coords  = (const float*)d_in[1];
    const int*   ei      = (const int*)  d_in[2];
    const int*   bt      = (const int*)  d_in[3];
    const float* W_nb    = (const float*)d_in[4];
    const float* b_nb    = (const float*)d_in[5];
    const float* W_nout  = (const float*)d_in[6];
    const float* b_nout  = (const float*)d_in[7];
    const float* conv_w  = (const float*)d_in[8];
    const float* conv_b  = (const float*)d_in[9];
    const float* W_el    = (const float*)d_in[10];
    const float* b_el    = (const float*)d_in[11];
    const float* W_eout  = (const float*)d_in[12];
    const float* b_eout  = (const float*)d_in[13];
    const float* W_coord = (const float*)d_in[14];
    const float* b_coord = (const float*)d_in[15];
    const float* W_pair  = (const float*)d_in[16];
    const float* b_pair  = (const float*)d_in[17];
    const float* W_sout  = (const float*)d_in[18];
    const float* b_sout  = (const float*)d_in[19];
    const float* W_init  = (const float*)d_in[20];
    const float* feat_lin= (const float*)d_in[21];
    const float* W_att   = (const float*)d_in[22];
    const float* W_agg   = (const float*)d_in[23];
    const float* gamma   = (const float*)d_in[24];
    const float* beta    = (const float*)d_in[25];

    const int N = in_sizes[0] / 128;
    const int E = in_sizes[2] / 2;

    static bool attrSet = false;
    if (!attrSet) {
        cudaFuncSetAttribute(mma_gemm,
            cudaFuncAttributeMaxDynamicSharedMemorySize, GEMM_SMEM);
        attrSet = true;
    }

    float* Un    = symaddr(g_b0);
    float* Vn    = symaddr(g_b1);
    float* Ue    = symaddr(g_b2);
    float* Ve    = symaddr(g_b3);
    float* Hagg  = symaddr(g_b4);
    float* Einit = symaddr(g_b5);
    float* Pn    = symaddr(g_b6);
    float* Pe    = symaddr(g_b7);
    float* T     = symaddr(g_b8);
    float* Fn    = symaddr(g_b9);
    float* Fe    = symaddr(g_b10);
    float* Fs    = symaddr(g_b13);
    float* sArr  = symaddr(g_s);
    float* dArr  = symaddr(g_deg);
    float* bnS   = symaddr(g_bnsum);
    float* bnQ   = symaddr(g_bnsq);
    float* E0 = Un; float* E1 = Vn; float* E2 = Ue;

    cudaMemsetAsync(bnS, 0, 128 * sizeof(float));
    cudaMemsetAsync(bnQ, 0, 128 * sizeof(float));

    // Weight indices in g_wt:
    //  0 Wnb_top  1 Wnb_bot  2 Wel_top  3 Wel_bot  4 W_init  5 Watt_top
    //  6 W_nout   7 W_eout   8 Wc_top   9 Wc_bot  10 W_pair 11 Ws_top
    // 12 Ws_bot  13 fl0     14 fl1     15 fl2     16 Watt_bot 17 W_agg
    WPtrs wp;
    wp.p[0]  = W_nb;               wp.p[1]  = W_nb + 128 * 128;
    wp.p[2]  = W_el;               wp.p[3]  = W_el + 128 * 128;
    wp.p[4]  = W_init;             wp.p[5]  = W_att;
    wp.p[6]  = W_nout;             wp.p[7]  = W_eout;
    wp.p[8]  = W_coord;            wp.p[9]  = W_coord + 128 * 128;
    wp.p[10] = W_pair;             wp.p[11] = W_sout;
    wp.p[12] = W_sout + 128 * 128; wp.p[13] = feat_lin;
    wp.p[14] = feat_lin + 128 * 128; wp.p[15] = feat_lin + 2 * 128 * 128;
    wp.p[16] = W_att + 128 * 128;  wp.p[17] = W_agg;

    setup_weights<<<dim3(18, 8), 256>>>(wp);

    dim3 gb(256);
    dim3 gg((N + 63) / 64);

    JobList jl;

    // --- L1: 4 projections + (Hini chain -> Einit); job0 also zeroes
    //     Pn/Pe/T/s/deg rows (replaces serialized memsets) ---
    jl.count = 6;
    jl.j[0] = mkjob(x, 0, Un,   0, b_nb, 1);
    jl.j[0].zeroAcc = 1;
    jl.j[1] = mkjob(x, 1, Vn,   0, nullptr, 0);
    jl.j[2] = mkjob(x, 2, Ue,   0, nullptr, 0);
    jl.j[3] = mkjob(x, 3, Ve,   0, nullptr, 0);
    jl.j[4] = mkjob(x, 4, nullptr, 2, nullptr, 0, nullptr, -1, nullptr, nullptr, nullptr, 1);
    jl.j[5] = mkjob(x, 5, Einit, 0, nullptr, 0);   // consumes chained Hini
    mma_gemm<<<gg, gb, GEMM_SMEM>>>(jl, N);

    // --- edge phase: ONE fused launch, ne-blocks + struct-blocks co-resident ---
    int gNE = (E + 15) / 16;
    int gST = (E + 31) / 32;
    edge_fused<<<gNE + gST, 256>>>(ei, bt, conv_w, conv_b, b_el, coords,
                                   (const float4*)x,
                                   (const float4*)Un, (const float4*)Vn,
                                   (const float4*)Ue, (const float4*)Ve,
                                   (float4*)Pn, (float4*)Pe, (float4*)T,
                                   sArr, dArr, E, gNE);

    // --- L2+L3 merged (all row deps are CTA-local) ---
    jl.count = 12;
    jl.j[0]  = mkjob(Pn, 6, Fn, 1, b_nout, 1);
    jl.j[1]  = mkjob(Pe, 7, Fe, 1, b_eout, 1);
    jl.j[2]  = mkjob(x, 8, nullptr, 0, b_coord, 1, T, 9, sArr, dArr, nullptr, 1);
    jl.j[3]  = mkjob(nullptr, 10, nullptr, 1, b_pair, 0, nullptr, -1, nullptr, nullptr, nullptr, 1);
    jl.j[4]  = mkjob(x, 12, Fs, 1, b_sout, 0, x, 11);
    jl.j[5]  = mkjob(Fn, 13, nullptr, 2, nullptr, 1, nullptr, -1, nullptr, nullptr, nullptr, 1);
    jl.j[6]  = mkjob(x, 16, E0, 0, nullptr, 0, nullptr, -1, nullptr, nullptr, Einit);
    jl.j[7]  = mkjob(Fe, 14, nullptr, 2, nullptr, 1, nullptr, -1, nullptr, nullptr, nullptr, 1);
    jl.j[8]  = mkjob(x, 16, E1, 0, nullptr, 0, nullptr, -1, nullptr, nullptr, Einit);
    jl.j[9]  = mkjob(Fs, 15, nullptr, 2, nullptr, 1, nullptr, -1, nullptr, nullptr, nullptr, 1);
    jl.j[10] = mkjob(x, 16, E2, 0, nullptr, 0, nullptr, -1, nullptr, nullptr, Einit);
    jl.j[11] = mkjob(E0, 17, Hagg, 0);
    jl.j[11].attn = 1; jl.j[11].bnstat = 1;
    jl.j[11].aE1 = E1; jl.j[11].aE2 = E2;
    jl.j[11].aF0 = Fn; jl.j[11].aF1 = Fe; jl.j[11].aF2 = Fs;
    mma_gemm<<<gg, gb, GEMM_SMEM>>>(jl, N);

    final_kernel<<<(N * 128 + 255) / 256, 256>>>(Hagg, bnS, bnQ, gamma, beta,
                                                 (float*)d_out, N);
}

// round 14
// speedup vs baseline: 1.6003x; 1.6003x over previous
#include <cuda_runtime.h>
#include <cuda_bf16.h>
#include <cstdint>

// ---------------------------------------------------------------------------
// MultiPathLayer: N=50000 nodes, E=800000 edges, D=128.
// GEMMs via mma.sync bf16 (split-bf16, fp32 accuracy), ldmatrix, cp.async
// hi/lo double-buffered (R12 config: 104KB smem, 2 CTAs/SM — 3 CTAs/SM
// provably spills the accumulator). Smem chain-fusion, fused attention +
// BN stats + accumulator zeroing. Edge phase: single fused launch.
// ---------------------------------------------------------------------------

#define NMAX 50000
#define DDIM 128
#define WPAD 136           // padded row length in bf16 elems — LDSM conflict-free
#define WELEMS (128 * WPAD)

__device__ float4 g_b0 [NMAX * 32];   // Un   -> later E0
__device__ float4 g_b1 [NMAX * 32];   // Vn   -> later E1
__device__ float4 g_b2 [NMAX * 32];   // Ue   -> later E2
__device__ float4 g_b3 [NMAX * 32];   // Ve
__device__ float4 g_b4 [NMAX * 32];   // Hagg
__device__ float4 g_b5 [NMAX * 32];   // Einit
__device__ float4 g_b6 [NMAX * 32];   // Pn
__device__ float4 g_b7 [NMAX * 32];   // Pe
__device__ float4 g_b8 [NMAX * 32];   // T
__device__ float4 g_b9 [NMAX * 32];   // Fn
__device__ float4 g_b10[NMAX * 32];   // Fe
__device__ float4 g_b13[NMAX * 32];   // Fs
__device__ float  g_s[NMAX];
__device__ float  g_deg[NMAX];
__device__ float  g_bnsum[DDIM];
__device__ float  g_bnsq[DDIM];

// Pre-converted weights: [weight][hi/lo][n*WPAD + k] (B operand layout [n][k]).
__device__ __align__(16) __nv_bfloat16 g_wt[18][2][WELEMS];

__device__ __forceinline__ float mishf(float x) {
    float e  = __expf(fminf(x, 30.0f));
    float t  = 1.0f + e;
    float t2 = t * t;
    return x * __fdividef(t2 - 1.0f, t2 + 1.0f);
}

__device__ __forceinline__ void red_add_v4(float4* p, float4 v) {
    asm volatile("red.global.add.v4.f32 [%0], {%1,%2,%3,%4};"
                 :: "l"(p), "f"(v.x), "f"(v.y), "f"(v.z), "f"(v.w)
                 : "memory");
}

__device__ __forceinline__ uint32_t smem_u32(const void* p) {
    uint32_t a;
    asm("{ .reg .u64 t; cvta.to.shared.u64 t, %1; cvt.u32.u64 %0, t; }"
        : "=r"(a) : "l"(p));
    return a;
}

__device__ __forceinline__ void mma_bf16(float* c, const uint32_t* a,
                                         const uint32_t* b) {
    asm volatile(
        "mma.sync.aligned.m16n8k16.row.col.f32.bf16.bf16.f32 "
        "{%0,%1,%2,%3}, {%4,%5,%6,%7}, {%8,%9}, {%0,%1,%2,%3};"
        : "+f"(c[0]), "+f"(c[1]), "+f"(c[2]), "+f"(c[3])
        : "r"(a[0]), "r"(a[1]), "r"(a[2]), "r"(a[3]), "r"(b[0]), "r"(b[1]));
}

__device__ __forceinline__ void ldsm4(uint32_t* r, uint32_t addr) {
    asm volatile("ldmatrix.sync.aligned.m8n8.x4.shared.b16 {%0,%1,%2,%3}, [%4];"
        : "=r"(r[0]), "=r"(r[1]), "=r"(r[2]), "=r"(r[3]) : "r"(addr));
}

__device__ __forceinline__ void cp_async16(uint32_t saddr, const void* g) {
    asm volatile("cp.async.cg.shared.global [%0], [%1], 16;"
                 :: "r"(saddr), "l"(g) : "memory");
}

// softmax over 3 logits, weighted sum of 3 features (scalar)
__device__ __forceinline__ float att3(float e0, float e1, float e2,
                                      float f0, float f1, float f2) {
    float m = fmaxf(e0, fmaxf(e1, e2));
    float p0 = __expf(e0 - m), p1 = __expf(e1 - m), p2 = __expf(e2 - m);
    return __fdividef(p0 * f0 + p1 * f1 + p2 * f2, p0 + p1 + p2);
}

// ---------------------------------------------------------------------------
// Weight setup.
// ---------------------------------------------------------------------------
struct WPtrs { const float* p[18]; };

__global__ void setup_weights(WPtrs wp)
{
    int w = blockIdx.x;
    const float* W = wp.p[w];
    __nv_bfloat16* hi = g_wt[w][0];
    __nv_bfloat16* lo = g_wt[w][1];
    for (int it = 0; it < 8; ++it) {
        int idx = blockIdx.y * 2048 + it * 256 + threadIdx.x;
        int k = idx >> 7;
        int n = idx & 127;
        float v = W[idx];
        __nv_bfloat16 h = __float2bfloat16(v);
        __nv_bfloat16 l = __float2bfloat16(v - __bfloat162float(h));
        hi[n * WPAD + k] = h;
        lo[n * WPAD + k] = l;
    }
}

// ---------------------------------------------------------------------------
// Fused edge phase: blocks [0, gNE) do node+edge paths (2 edges/warp),
// blocks [gNE, ...) do struct path (4 edges/warp).
// ---------------------------------------------------------------------------
__global__ void __launch_bounds__(256) edge_fused(
    const int*   __restrict__ ei,
    const int*   __restrict__ bt,
    const float* __restrict__ conv_w,
    const float* __restrict__ conv_b,
    const float* __restrict__ b_el,
    const float* __restrict__ coords,
    const float4* __restrict__ x,
    const float4* __restrict__ Un, const float4* __restrict__ Vn,
    const float4* __restrict__ Ue, const float4* __restrict__ Ve,
    float4* Pn, float4* Pe, float4* T,
    float* s_arr, float* deg_arr, int E, int gNE)
{
    int lane = threadIdx.x & 31;

    if ((int)blockIdx.x < gNE) {
        int base = (blockIdx.x * 8 + (threadIdx.x >> 5)) * 2;
        if (base >= E) return;
        int e1ok = (base + 1 < E);

        int src0 = ei[base];
        int dst0 = ei[E + base];
        int src1 = e1ok ? ei[base + 1]     : src0;
        int dst1 = e1ok ? ei[E + base + 1] : dst0;
        float norm0 = conv_w[bt[base]] + conv_b[0];
        float norm1 = conv_w[bt[e1ok ? base + 1 : base]] + conv_b[0];

        int di0 = dst0 * 32 + lane, si0 = src0 * 32 + lane;
        int di1 = dst1 * 32 + lane, si1 = src1 * 32 + lane;

        float4 un0 = Un[di0];
        float4 vn0 = Vn[si0];
        float4 ue0 = Ue[di0];
        float4 ve0 = Ve[si0];
        float4 un1 = Un[di1];
        float4 vn1 = Vn[si1];
        float4 ue1 = Ue[di1];
        float4 ve1 = Ve[si1];
        float4 b   = ((const float4*)b_el)[lane];

        float4 m;
        m.x = mishf(un0.x + vn0.x); m.y = mishf(un0.y + vn0.y);
        m.z = mishf(un0.z + vn0.z); m.w = mishf(un0.w + vn0.w);
        red_add_v4(&Pn[di0], m);

        m.x = mishf(norm0 * (ue0.x + ve0.x) + b.x);
        m.y = mishf(norm0 * (ue0.y + ve0.y) + b.y);
        m.z = mishf(norm0 * (ue0.z + ve0.z) + b.z);
        m.w = mishf(norm0 * (ue0.w + ve0.w) + b.w);
        red_add_v4(&Pe[di0], m);

        if (e1ok) {
            m.x = mishf(un1.x + vn1.x); m.y = mishf(un1.y + vn1.y);
            m.z = mishf(un1.z + vn1.z); m.w = mishf(un1.w + vn1.w);
            red_add_v4(&Pn[di1], m);

            m.x = mishf(norm1 * (ue1.x + ve1.x) + b.x);
            m.y = mishf(norm1 * (ue1.y + ve1.y) + b.y);
            m.z = mishf(norm1 * (ue1.z + ve1.z) + b.z);
            m.w = mishf(norm1 * (ue1.w + ve1.w) + b.w);
            red_add_v4(&Pe[di1], m);
        }
    } else {
        int bid = blockIdx.x - gNE;
        int base = (bid * 8 + (threadIdx.x >> 5)) * 4;
        if (base >= E) return;
        int cnt = min(4, E - base);

        int src[4], dst[4];
        float d2[4];
        #pragma unroll
        for (int q = 0; q < 4; ++q) {
            int e = base + ((q < cnt) ? q : 0);
            src[q] = ei[e];
            dst[q] = ei[E + e];
        }
        #pragma unroll
        for (int q = 0; q < 4; ++q) {
            float dx = coords[src[q] * 3 + 0] - coords[dst[q] * 3 + 0];
            float dy = coords[src[q] * 3 + 1] - coords[dst[q] * 3 + 1];
            float dz = coords[src[q] * 3 + 2] - coords[dst[q] * 3 + 2];
            d2[q] = dx * dx + dy * dy + dz * dz;
        }
        float4 xs[4];
        #pragma unroll
        for (int q = 0; q < 4; ++q)
            xs[q] = x[src[q] * 32 + lane];

        #pragma unroll
        for (int q = 0; q < 4; ++q) {
            if (q >= cnt) break;
            float4 m = make_float4(d2[q] * xs[q].x, d2[q] * xs[q].y,
                                   d2[q] * xs[q].z, d2[q] * xs[q].w);
            red_add_v4(&T[dst[q] * 32 + lane], m);
            if (lane == 0) {
                atomicAdd(&s_arr[dst[q]], d2[q]);
                atomicAdd(&deg_arr[dst[q]], 1.0f);
            }
        }
    }
}

// ---------------------------------------------------------------------------
// Batched / chain-fused mma.sync GEMM (R12 config: double-buffered B,
// 104448 B smem, 2 CTAs/SM — do NOT force 3; the accumulator spills).
// ---------------------------------------------------------------------------
struct Job {
    const float* A; const float* A2;
    const float* rowScale; const float* bias;
    const float* biasRowScale; const float* Cadd;
    const float* aE1; const float* aE2;
    const float* aF0; const float* aF1; const float* aF2;
    float* C;
    int w1, w2, actMode, convertA, chainOut, attn, bnstat, zeroAcc;
};
struct JobList { Job j[12]; int count; };

__global__ void __launch_bounds__(256, 2) mma_gemm(JobList jl, int n)
{
    extern __shared__ __nv_bfloat16 sm[];
    const int tid  = threadIdx.x;
    const int wid  = tid >> 5;
    const int lane = tid & 31;
    const int tq = lane >> 2;
    const int tr = lane & 3;
    const int warpM = wid >> 2;     // 0..1
    const int warpN = wid & 3;      // 0..3
    const int rowBase = blockIdx.x * 64;

    const uint32_t smBase  = smem_u32(sm);
    const uint32_t aHiAddr = smBase;
    const uint32_t aLoAddr = smBase + 17408;
    const uint32_t bHiAddr = smBase + 34816;
    const uint32_t bLoAddr = smBase + 69632;

    const uint32_t aoff0 = ((warpM * 32 + (lane & 15)) * WPAD + (lane >> 4) * 8) * 2;
    const uint32_t aoff1 = aoff0 + 16 * WPAD * 2;
    const int bRow = warpN * 32 + ((lane >> 4) << 3) + (lane & 7);
    const uint32_t boff0 = (bRow * WPAD + ((lane >> 3) & 1) * 8) * 2;
    const uint32_t boff1 = boff0 + 16 * WPAD * 2;

    for (int ji = 0; ji < jl.count; ++ji) {
        const Job J = jl.j[ji];

        float acc[2][4][4];
        #pragma unroll
        for (int i = 0; i < 2; ++i)
            #pragma unroll
            for (int j = 0; j < 4; ++j)
                #pragma unroll
                for (int q = 0; q < 4; ++q) acc[i][j][q] = 0.0f;

        const int passes = (J.A2 != nullptr) ? 2 : 1;
        for (int p = 0; p < passes; ++p) {
            const float* Ap  = p ? J.A2 : J.A;
            const float* rsp = p ? nullptr : J.rowScale;
            const bool doConv = (p == 1) || (J.convertA != 0);
            const int  w = p ? J.w2 : J.w1;

            __syncthreads();   // previous mainloop / chain writes done

            // --- B prefetch: hi group then lo group ---
            {
                const char* src = (const char*)g_wt[w] + tid * 16;
                uint32_t dst = bHiAddr + tid * 16;
                #pragma unroll
                for (int it = 0; it < 9; ++it)
                    cp_async16(dst + it * 4096, src + it * 4096);
                asm volatile("cp.async.commit_group;" ::: "memory");
                #pragma unroll
                for (int it = 9; it < 17; ++it)
                    cp_async16(dst + it * 4096, src + it * 4096);
                asm volatile("cp.async.commit_group;" ::: "memory");
            }

            // --- A tile: 64x128 -> hi/lo bf16 (overlaps B prefetch) ---
            if (doConv) {
                #pragma unroll
                for (int it = 0; it < 8; ++it) {
                    int idx = tid + (it << 8);
                    int row = idx >> 5;
                    int c4  = idx & 31;
                    int grow = rowBase + row;
                    float4 v = make_float4(0.f, 0.f, 0.f, 0.f);
                    if (grow < n) {
                        int gi = grow * 32 + c4;
                        if (J.attn) {
                            float4 e0 = ((const float4*)Ap)[gi];
                            float4 e1 = ((const float4*)J.aE1)[gi];
                            float4 e2 = ((const float4*)J.aE2)[gi];
                            float4 f0 = ((const float4*)J.aF0)[gi];
                            float4 f1 = ((const float4*)J.aF1)[gi];
                            float4 f2 = ((const float4*)J.aF2)[gi];
                            v.x = att3(e0.x, e1.x, e2.x, f0.x, f1.x, f2.x);
                            v.y = att3(e0.y, e1.y, e2.y, f0.y, f1.y, f2.y);
                            v.z = att3(e0.z, e1.z, e2.z, f0.z, f1.z, f2.z);
                            v.w = att3(e0.w, e1.w, e2.w, f0.w, f1.w, f2.w);
                        } else {
                            v = ((const float4*)Ap)[gi];
                            if (rsp) {
                                float s = __ldg(&rsp[grow]);
                                v.x *= s; v.y *= s; v.z *= s; v.w *= s;
                            }
                        }
                    }
                    __nv_bfloat16 hx = __float2bfloat16(v.x);
                    __nv_bfloat16 hy = __float2bfloat16(v.y);
                    __nv_bfloat16 hz = __float2bfloat16(v.z);
                    __nv_bfloat16 hw = __float2bfloat16(v.w);
                    __nv_bfloat162 h01; h01.x = hx; h01.y = hy;
                    __nv_bfloat162 h23; h23.x = hz; h23.y = hw;
                    __nv_bfloat162 l01, l23;
                    l01.x = __float2bfloat16(v.x - __bfloat162float(hx));
                    l01.y = __float2bfloat16(v.y - __bfloat162float(hy));
                    l23.x = __float2bfloat16(v.z - __bfloat162float(hz));
                    l23.y = __float2bfloat16(v.w - __bfloat162float(hw));
                    int o = row * WPAD + c4 * 4;
                    *(__nv_bfloat162*)&sm[o]            = h01;
                    *(__nv_bfloat162*)&sm[o + 2]        = h23;
                    *(__nv_bfloat162*)&sm[8704 + o]     = l01;
                    *(__nv_bfloat162*)&sm[8704 + o + 2] = l23;
                }
            }
            // B_hi arrived (lo still pending)
            asm volatile("cp.async.wait_group 1;" ::: "memory");
            __syncthreads();

            // --- split terms using B_hi: hi_a·hi_b, lo_a·hi_b ---
            #pragma unroll
            for (int sel = 0; sel < 2; ++sel) {
                const uint32_t aB = (sel == 1) ? aLoAddr : aHiAddr;
                #pragma unroll
                for (int kk = 0; kk < 8; ++kk) {
                    uint32_t ko = kk * 32;
                    uint32_t a0[4], a1[4], b0[4], b1[4];
                    ldsm4(a0, aB + aoff0 + ko);
                    ldsm4(a1, aB + aoff1 + ko);
                    ldsm4(b0, bHiAddr + boff0 + ko);
                    ldsm4(b1, bHiAddr + boff1 + ko);
                    mma_bf16(acc[0][0], a0, &b0[0]);
                    mma_bf16(acc[0][1], a0, &b0[2]);
                    mma_bf16(acc[0][2], a0, &b1[0]);
                    mma_bf16(acc[0][3], a0, &b1[2]);
                    mma_bf16(acc[1][0], a1, &b0[0]);
                    mma_bf16(acc[1][1], a1, &b0[2]);
                    mma_bf16(acc[1][2], a1, &b1[0]);
                    mma_bf16(acc[1][3], a1, &b1[2]);
                }
            }
            // B_lo arrived
            asm volatile("cp.async.wait_group 0;" ::: "memory");
            __syncthreads();

            // --- split term hi_a·lo_b ---
            #pragma unroll
            for (int kk = 0; kk < 8; ++kk) {
                uint32_t ko = kk * 32;
                uint32_t a0[4], a1[4], b0[4], b1[4];
                ldsm4(a0, aHiAddr + aoff0 + ko);
                ldsm4(a1, aHiAddr + aoff1 + ko);
                ldsm4(b0, bLoAddr + boff0 + ko);
                ldsm4(b1, bLoAddr + boff1 + ko);
                mma_bf16(acc[0][0], a0, &b0[0]);
                mma_bf16(acc[0][1], a0, &b0[2]);
                mma_bf16(acc[0][2], a0, &b1[0]);
                mma_bf16(acc[0][3], a0, &b1[2]);
                mma_bf16(acc[1][0], a1, &b0[0]);
                mma_bf16(acc[1][1], a1, &b0[2]);
                mma_bf16(acc[1][2], a1, &b1[0]);
                mma_bf16(acc[1][3], a1, &b1[2]);
            }
        }

        if (J.chainOut) {
            __syncthreads();   // all warps done reading A smem
            #pragma unroll
            for (int mt = 0; mt < 2; ++mt) {
                #pragma unroll
                for (int half = 0; half < 2; ++half) {
                    int rloc = warpM * 32 + mt * 16 + tq + half * 8;
                    #pragma unroll
                    for (int nt = 0; nt < 4; ++nt) {
                        int col = warpN * 32 + nt * 8 + tr * 2;
                        float v0 = acc[mt][nt][half * 2];
                        float v1 = acc[mt][nt][half * 2 + 1];
                        if (J.bias) {
                            v0 += __ldg(&J.bias[col]);
                            v1 += __ldg(&J.bias[col + 1]);
                        }
                        if (J.actMode == 1)      { v0 = mishf(v0); v1 = mishf(v1); }
                        else if (J.actMode == 2) { v0 = mishf(mishf(v0)); v1 = mishf(mishf(v1)); }
                        __nv_bfloat16 h0 = __float2bfloat16(v0);
                        __nv_bfloat16 h1 = __float2bfloat16(v1);
                        __nv_bfloat162 hh; hh.x = h0; hh.y = h1;
                        __nv_bfloat162 ll;
                        ll.x = __float2bfloat16(v0 - __bfloat162float(h0));
                        ll.y = __float2bfloat16(v1 - __bfloat162float(h1));
                        int o = rloc * WPAD + col;
                        *(__nv_bfloat162*)&sm[o]        = hh;
                        *(__nv_bfloat162*)&sm[8704 + o] = ll;
                    }
                }
            }
        } else {
            float* scol = (float*)sm;          // [128] sums, [128] sumsq
            if (J.bnstat) {
                __syncthreads();               // mainloop smem reads done
                if (tid < 256) scol[tid] = 0.0f;
                __syncthreads();
            }
            float cs[8], cq[8];
            #pragma unroll
            for (int q = 0; q < 8; ++q) { cs[q] = 0.f; cq[q] = 0.f; }

            #pragma unroll
            for (int mt = 0; mt < 2; ++mt) {
                #pragma unroll
                for (int half = 0; half < 2; ++half) {
                    int grow = rowBase + warpM * 32 + mt * 16 + tq + half * 8;
                    if (grow >= n) continue;
                    float brs = J.biasRowScale ? __ldg(&J.biasRowScale[grow]) : 1.0f;
                    #pragma unroll
                    for (int nt = 0; nt < 4; ++nt) {
                        int col = warpN * 32 + nt * 8 + tr * 2;
                        float v0 = acc[mt][nt][half * 2];
                        float v1 = acc[mt][nt][half * 2 + 1];
                        if (J.bias) {
                            v0 += __ldg(&J.bias[col])     * brs;
                            v1 += __ldg(&J.bias[col + 1]) * brs;
                        }
                        if (J.Cadd) {
                            float2 ca = *(const float2*)&J.Cadd[grow * 128 + col];
                            v0 += ca.x; v1 += ca.y;
                        }
                        if (J.actMode == 1)      { v0 = mishf(v0); v1 = mishf(v1); }
                        else if (J.actMode == 2) { v0 = mishf(mishf(v0)); v1 = mishf(mishf(v1)); }
                        *(float2*)&J.C[grow * 128 + col] = make_float2(v0, v1);
                        if (J.bnstat) {
                            cs[nt * 2]     += v0; cq[nt * 2]     += v0 * v0;
                            cs[nt * 2 + 1] += v1; cq[nt * 2 + 1] += v1 * v1;
                        }
                    }
                }
            }
            if (J.bnstat) {
                #pragma unroll
                for (int nt = 0; nt < 4; ++nt) {
                    int col = warpN * 32 + nt * 8 + tr * 2;
                    atomicAdd(&scol[col],           cs[nt * 2]);
                    atomicAdd(&scol[col + 1],       cs[nt * 2 + 1]);
                    atomicAdd(&scol[128 + col],     cq[nt * 2]);
                    atomicAdd(&scol[128 + col + 1], cq[nt * 2 + 1]);
                }
                __syncthreads();
                if (tid < 128) {
                    atomicAdd(&g_bnsum[tid], scol[tid]);
                    atomicAdd(&g_bnsq[tid],  scol[128 + tid]);
                }
            }
            if (J.zeroAcc) {
                float4 z = make_float4(0.f, 0.f, 0.f, 0.f);
                #pragma unroll
                for (int it = 0; it < 8; ++it) {
                    int idx = tid + (it << 8);
                    int row = idx >> 5;
                    int c   = idx & 31;
                    int grow = rowBase + row;
                    if (grow < n) {
                        g_b6[grow * 32 + c] = z;
                        g_b7[grow * 32 + c] = z;
                        g_b8[grow * 32 + c] = z;
                    }
                }
                if (tid < 64) {
                    int grow = rowBase + tid;
                    if (grow < n) { g_s[grow] = 0.f; g_deg[grow] = 0.f; }
                }
            }
        }
    }
}

// ---------------------------------------------------------------------------
// Final BN + mish, float4-vectorized (4 columns per thread).
// ---------------------------------------------------------------------------
__global__ void final_kernel(const float4* __restrict__ H,
                             const float4* __restrict__ sum,
                             const float4* __restrict__ sq,
                             const float4* __restrict__ gamma,
                             const float4* __restrict__ beta,
                             float4* __restrict__ out, int n)
{
    int i = blockIdx.x * blockDim.x + threadIdx.x;
    if (i >= n * 32) return;
    int d4 = i & 31;
    float invn = 1.0f / (float)n;
    float4 s = sum[d4], q = sq[d4], g = gamma[d4], b = beta[d4];
    float4 h = H[i];
    float4 o;
    {
        float mean = s.x * invn;
        float var  = q.x * invn - mean * mean;
        o.x = mishf((h.x - mean) * rsqrtf(var + 1e-5f) * g.x + b.x);
    }
    {
        float mean = s.y * invn;
        float var  = q.y * invn - mean * mean;
        o.y = mishf((h.y - mean) * rsqrtf(var + 1e-5f) * g.y + b.y);
    }
    {
        float mean = s.z * invn;
        float var  = q.z * invn - mean * mean;
        o.z = mishf((h.z - mean) * rsqrtf(var + 1e-5f) * g.z + b.z);
    }
    {
        float mean = s.w * invn;
        float var  = q.w * invn - mean * mean;
        o.w = mishf((h.w - mean) * rsqrtf(var + 1e-5f) * g.w + b.w);
    }
    out[i] = o;
}

// ---------------------------------------------------------------------------
// Host launch
// ---------------------------------------------------------------------------
static float* symaddr(const void* sym) {
    void* p = nullptr;
    cudaGetSymbolAddress(&p, sym);
    return (float*)p;
}

#define GEMM_SMEM 104448

static Job mkjob(const float* A, int w1, float* C, int act,
                 const float* bias = nullptr, int convertA = 1,
                 const float* A2 = nullptr, int w2 = -1,
                 const float* rowScale = nullptr,
                 const float* brs = nullptr, const float* Cadd = nullptr,
                 int chainOut = 0)
{
    Job j;
    j.A = A; j.A2 = A2; j.rowScale = rowScale; j.bias = bias;
    j.biasRowScale = brs; j.Cadd = Cadd; j.C = C;
    j.aE1 = nullptr; j.aE2 = nullptr;
    j.aF0 = nullptr; j.aF1 = nullptr; j.aF2 = nullptr;
    j.w1 = w1; j.w2 = w2; j.actMode = act; j.convertA = convertA;
    j.chainOut = chainOut; j.attn = 0; j.bnstat = 0; j.zeroAcc = 0;
    return j;
}

extern "C" void kernel_launch(void* const* d_in, const int* in_sizes, int n_in,
                              void* d_out, int out_size)
{
    const float* x       = (const float*)d_in[0];
    const float* coords  = (const float*)d_in[1];
    const int*   ei      = (const int*)  d_in[2];
    const int*   bt      = (const int*)  d_in[3];
    const float* W_nb    = (const float*)d_in[4];
    const float* b_nb    = (const float*)d_in[5];
    const float* W_nout  = (const float*)d_in[6];
    const float* b_nout  = (const float*)d_in[7];
    const float* conv_w  = (const float*)d_in[8];
    const float* conv_b  = (const float*)d_in[9];
    const float* W_el    = (const float*)d_in[10];
    const float* b_el    = (const float*)d_in[11];
    const float* W_eout  = (const float*)d_in[12];
    const float* b_eout  = (const float*)d_in[13];
    const float* W_coord = (const float*)d_in[14];
    const float* b_coord = (const float*)d_in[15];
    const float* W_pair  = (const float*)d_in[16];
    const float* b_pair  = (const float*)d_in[17];
    const float* W_sout  = (const float*)d_in[18];
    const float* b_sout  = (const float*)d_in[19];
    const float* W_init  = (const float*)d_in[20];
    const float* feat_lin= (const float*)d_in[21];
    const float* W_att   = (const float*)d_in[22];
    const float* W_agg   = (const float*)d_in[23];
    const float* gamma   = (const float*)d_in[24];
    const float* beta    = (const float*)d_in[25];

    const int N = in_sizes[0] / 128;
    const int E = in_sizes[2] / 2;

    static bool attrSet = false;
    if (!attrSet) {
        cudaFuncSetAttribute(mma_gemm,
            cudaFuncAttributeMaxDynamicSharedMemorySize, GEMM_SMEM);
        attrSet = true;
    }

    float* Un    = symaddr(g_b0);
    float* Vn    = symaddr(g_b1);
    float* Ue    = symaddr(g_b2);
    float* Ve    = symaddr(g_b3);
    float* Hagg  = symaddr(g_b4);
    float* Einit = symaddr(g_b5);
    float* Pn    = symaddr(g_b6);
    float* Pe    = symaddr(g_b7);
    float* T     = symaddr(g_b8);
    float* Fn    = symaddr(g_b9);
    float* Fe    = symaddr(g_b10);
    float* Fs    = symaddr(g_b13);
    float* sArr  = symaddr(g_s);
    float* dArr  = symaddr(g_deg);
    float* bnS   = symaddr(g_bnsum);
    float* bnQ   = symaddr(g_bnsq);
    float* E0 = Un; float* E1 = Vn; float* E2 = Ue;

    cudaMemsetAsync(bnS, 0, 128 * sizeof(float));
    cudaMemsetAsync(bnQ, 0, 128 * sizeof(float));

    // Weight indices in g_wt:
    //  0 Wnb_top  1 Wnb_bot  2 Wel_top  3 Wel_bot  4 W_init  5 Watt_top
    //  6 W_nout   7 W_eout   8 Wc_top   9 Wc_bot  10 W_pair 11 Ws_top
    // 12 Ws_bot  13 fl0     14 fl1     15 fl2     16 Watt_bot 17 W_agg
    WPtrs wp;
    wp.p[0]  = W_nb;               wp.p[1]  = W_nb + 128 * 128;
    wp.p[2]  = W_el;               wp.p[3]  = W_el + 128 * 128;
    wp.p[4]  = W_init;             wp.p[5]  = W_att;
    wp.p[6]  = W_nout;             wp.p[7]  = W_eout;
    wp.p[8]  = W_coord;            wp.p[9]  = W_coord + 128 * 128;
    wp.p[10] = W_pair;             wp.p[11] = W_sout;
    wp.p[12] = W_sout + 128 * 128; wp.p[13] = feat_lin;
    wp.p[14] = feat_lin + 128 * 128; wp.p[15] = feat_lin + 2 * 128 * 128;
    wp.p[16] = W_att + 128 * 128;  wp.p[17] = W_agg;

    setup_weights<<<dim3(18, 8), 256>>>(wp);

    dim3 gb(256);
    dim3 gg((N + 63) / 64);

    JobList jl;

    // --- L1: 4 projections + (Hini chain -> Einit); job0 also zeroes
    //     Pn/Pe/T/s/deg rows (replaces serialized memsets) ---
    jl.count = 6;
    jl.j[0] = mkjob(x, 0, Un,   0, b_nb, 1);
    jl.j[0].zeroAcc = 1;
    jl.j[1] = mkjob(x, 1, Vn,   0, nullptr, 0);
    jl.j[2] = mkjob(x, 2, Ue,   0, nullptr, 0);
    jl.j[3] = mkjob(x, 3, Ve,   0, nullptr, 0);
    jl.j[4] = mkjob(x, 4, nullptr, 2, nullptr, 0, nullptr, -1, nullptr, nullptr, nullptr, 1);
    jl.j[5] = mkjob(x, 5, Einit, 0, nullptr, 0);   // consumes chained Hini
    mma_gemm<<<gg, gb, GEMM_SMEM>>>(jl, N);

    // --- edge phase: ONE fused launch, ne-blocks + struct-blocks co-resident ---
    int gNE = (E + 15) / 16;
    int gST = (E + 31) / 32;
    edge_fused<<<gNE + gST, 256>>>(ei, bt, conv_w, conv_b, b_el, coords,
                                   (const float4*)x,
                                   (const float4*)Un, (const float4*)Vn,
                                   (const float4*)Ue, (const float4*)Ve,
                                   (float4*)Pn, (float4*)Pe, (float4*)T,
                                   sArr, dArr, E, gNE);

    // --- L2+L3 merged (all row deps are CTA-local) ---
    jl.count = 12;
    jl.j[0]  = mkjob(Pn, 6, Fn, 1, b_nout, 1);
    jl.j[1]  = mkjob(Pe, 7, Fe, 1, b_eout, 1);
    jl.j[2]  = mkjob(x, 8, nullptr, 0, b_coord, 1, T, 9, sArr, dArr, nullptr, 1);
    jl.j[3]  = mkjob(nullptr, 10, nullptr, 1, b_pair, 0, nullptr, -1, nullptr, nullptr, nullptr, 1);
    jl.j[4]  = mkjob(x, 12, Fs, 1, b_sout, 0, x, 11);
    jl.j[5]  = mkjob(Fn, 13, nullptr, 2, nullptr, 1, nullptr, -1, nullptr, nullptr, nullptr, 1);
    jl.j[6]  = mkjob(x, 16, E0, 0, nullptr, 0, nullptr, -1, nullptr, nullptr, Einit);
    jl.j[7]  = mkjob(Fe, 14, nullptr, 2, nullptr, 1, nullptr, -1, nullptr, nullptr, nullptr, 1);
    jl.j[8]  = mkjob(x, 16, E1, 0, nullptr, 0, nullptr, -1, nullptr, nullptr, Einit);
    jl.j[9]  = mkjob(Fs, 15, nullptr, 2, nullptr, 1, nullptr, -1, nullptr, nullptr, nullptr, 1);
    jl.j[10] = mkjob(x, 16, E2, 0, nullptr, 0, nullptr, -1, nullptr, nullptr, Einit);
    jl.j[11] = mkjob(E0, 17, Hagg, 0);
    jl.j[11].attn = 1; jl.j[11].bnstat = 1;
    jl.j[11].aE1 = E1; jl.j[11].aE2 = E2;
    jl.j[11].aF0 = Fn; jl.j[11].aF1 = Fe; jl.j[11].aF2 = Fs;
    mma_gemm<<<gg, gb, GEMM_SMEM>>>(jl, N);

    final_kernel<<<(N * 32 + 255) / 256, 256>>>(
        (const float4*)Hagg, (const float4*)bnS, (const float4*)bnQ,
        (const float4*)gamma, (const float4*)beta, (float4*)d_out, N);
}

// round 15
// speedup vs baseline: 1.6923x; 1.0574x over previous
#include <cuda_runtime.h>
#include <cuda_bf16.h>
#include <cstdint>

// ---------------------------------------------------------------------------
// MultiPathLayer: N=50000 nodes, E=800000 edges, D=128.
// GEMMs via mma.sync bf16 (split-bf16, fp32 accuracy), ldmatrix, cp.async
// hi/lo double-buffered (104KB smem, 2 CTAs/SM — 3 CTAs/SM spills).
// Einit/Hini ELIMINATED: the lin_init@W_att_top logit term is constant
// across the path axis and cancels in the softmax. Smem chain-fusion,
// fused attention + BN stats + accumulator zeroing; fused edge launch.
// ---------------------------------------------------------------------------

#define NMAX 50000
#define DDIM 128
#define WPAD 136           // padded row length in bf16 elems — LDSM conflict-free
#define WELEMS (128 * WPAD)

__device__ float4 g_b0 [NMAX * 32];   // Un   -> later E0
__device__ float4 g_b1 [NMAX * 32];   // Vn   -> later E1
__device__ float4 g_b2 [NMAX * 32];   // Ue   -> later E2
__device__ float4 g_b3 [NMAX * 32];   // Ve
__device__ float4 g_b4 [NMAX * 32];   // Hagg
__device__ float4 g_b6 [NMAX * 32];   // Pn
__device__ float4 g_b7 [NMAX * 32];   // Pe
__device__ float4 g_b8 [NMAX * 32];   // T
__device__ float4 g_b9 [NMAX * 32];   // Fn
__device__ float4 g_b10[NMAX * 32];   // Fe
__device__ float4 g_b13[NMAX * 32];   // Fs
__device__ float  g_s[NMAX];
__device__ float  g_deg[NMAX];
__device__ float  g_bnsum[DDIM];
__device__ float  g_bnsq[DDIM];

// Pre-converted weights: [weight][hi/lo][n*WPAD + k] (B operand layout [n][k]).
__device__ __align__(16) __nv_bfloat16 g_wt[18][2][WELEMS];

__device__ __forceinline__ float mishf(float x) {
    float e  = __expf(fminf(x, 30.0f));
    float t  = 1.0f + e;
    float t2 = t * t;
    return x * __fdividef(t2 - 1.0f, t2 + 1.0f);
}

__device__ __forceinline__ void red_add_v4(float4* p, float4 v) {
    asm volatile("red.global.add.v4.f32 [%0], {%1,%2,%3,%4};"
                 :: "l"(p), "f"(v.x), "f"(v.y), "f"(v.z), "f"(v.w)
                 : "memory");
}

__device__ __forceinline__ uint32_t smem_u32(const void* p) {
    uint32_t a;
    asm("{ .reg .u64 t; cvta.to.shared.u64 t, %1; cvt.u32.u64 %0, t; }"
        : "=r"(a) : "l"(p));
    return a;
}

__device__ __forceinline__ void mma_bf16(float* c, const uint32_t* a,
                                         const uint32_t* b) {
    asm volatile(
        "mma.sync.aligned.m16n8k16.row.col.f32.bf16.bf16.f32 "
        "{%0,%1,%2,%3}, {%4,%5,%6,%7}, {%8,%9}, {%0,%1,%2,%3};"
        : "+f"(c[0]), "+f"(c[1]), "+f"(c[2]), "+f"(c[3])
        : "r"(a[0]), "r"(a[1]), "r"(a[2]), "r"(a[3]), "r"(b[0]), "r"(b[1]));
}

__device__ __forceinline__ void ldsm4(uint32_t* r, uint32_t addr) {
    asm volatile("ldmatrix.sync.aligned.m8n8.x4.shared.b16 {%0,%1,%2,%3}, [%4];"
        : "=r"(r[0]), "=r"(r[1]), "=r"(r[2]), "=r"(r[3]) : "r"(addr));
}

__device__ __forceinline__ void cp_async16(uint32_t saddr, const void* g) {
    asm volatile("cp.async.cg.shared.global [%0], [%1], 16;"
                 :: "r"(saddr), "l"(g) : "memory");
}

// softmax over 3 logits, weighted sum of 3 features (scalar)
__device__ __forceinline__ float att3(float e0, float e1, float e2,
                                      float f0, float f1, float f2) {
    float m = fmaxf(e0, fmaxf(e1, e2));
    float p0 = __expf(e0 - m), p1 = __expf(e1 - m), p2 = __expf(e2 - m);
    return __fdividef(p0 * f0 + p1 * f1 + p2 * f2, p0 + p1 + p2);
}

// ---------------------------------------------------------------------------
// Weight setup.
// ---------------------------------------------------------------------------
struct WPtrs { const float* p[18]; };

__global__ void setup_weights(WPtrs wp)
{
    int w = blockIdx.x;
    const float* W = wp.p[w];
    __nv_bfloat16* hi = g_wt[w][0];
    __nv_bfloat16* lo = g_wt[w][1];
    for (int it = 0; it < 8; ++it) {
        int idx = blockIdx.y * 2048 + it * 256 + threadIdx.x;
        int k = idx >> 7;
        int n = idx & 127;
        float v = W[idx];
        __nv_bfloat16 h = __float2bfloat16(v);
        __nv_bfloat16 l = __float2bfloat16(v - __bfloat162float(h));
        hi[n * WPAD + k] = h;
        lo[n * WPAD + k] = l;
    }
}

// ---------------------------------------------------------------------------
// Fused edge phase: blocks [0, gNE) do node+edge paths (2 edges/warp),
// blocks [gNE, ...) do struct path (4 edges/warp).
// ---------------------------------------------------------------------------
__global__ void __launch_bounds__(256) edge_fused(
    const int*   __restrict__ ei,
    const int*   __restrict__ bt,
    const float* __restrict__ conv_w,
    const float* __restrict__ conv_b,
    const float* __restrict__ b_el,
    const float* __restrict__ coords,
    const float4* __restrict__ x,
    const float4* __restrict__ Un, const float4* __restrict__ Vn,
    const float4* __restrict__ Ue, const float4* __restrict__ Ve,
    float4* Pn, float4* Pe, float4* T,
    float* s_arr, float* deg_arr, int E, int gNE)
{
    int lane = threadIdx.x & 31;

    if ((int)blockIdx.x < gNE) {
        int base = (blockIdx.x * 8 + (threadIdx.x >> 5)) * 2;
        if (base >= E) return;
        int e1ok = (base + 1 < E);

        int src0 = ei[base];
        int dst0 = ei[E + base];
        int src1 = e1ok ? ei[base + 1]     : src0;
        int dst1 = e1ok ? ei[E + base + 1] : dst0;
        float norm0 = conv_w[bt[base]] + conv_b[0];
        float norm1 = conv_w[bt[e1ok ? base + 1 : base]] + conv_b[0];

        int di0 = dst0 * 32 + lane, si0 = src0 * 32 + lane;
        int di1 = dst1 * 32 + lane, si1 = src1 * 32 + lane;

        float4 un0 = Un[di0];
        float4 vn0 = Vn[si0];
        float4 ue0 = Ue[di0];
        float4 ve0 = Ve[si0];
        float4 un1 = Un[di1];
        float4 vn1 = Vn[si1];
        float4 ue1 = Ue[di1];
        float4 ve1 = Ve[si1];
        float4 b   = ((const float4*)b_el)[lane];

        float4 m;
        m.x = mishf(un0.x + vn0.x); m.y = mishf(un0.y + vn0.y);
        m.z = mishf(un0.z + vn0.z); m.w = mishf(un0.w + vn0.w);
        red_add_v4(&Pn[di0], m);

        m.x = mishf(norm0 * (ue0.x + ve0.x) + b.x);
        m.y = mishf(norm0 * (ue0.y + ve0.y) + b.y);
        m.z = mishf(norm0 * (ue0.z + ve0.z) + b.z);
        m.w = mishf(norm0 * (ue0.w + ve0.w) + b.w);
        red_add_v4(&Pe[di0], m);

        if (e1ok) {
            m.x = mishf(un1.x + vn1.x); m.y = mishf(un1.y + vn1.y);
            m.z = mishf(un1.z + vn1.z); m.w = mishf(un1.w + vn1.w);
            red_add_v4(&Pn[di1], m);

            m.x = mishf(norm1 * (ue1.x + ve1.x) + b.x);
            m.y = mishf(norm1 * (ue1.y + ve1.y) + b.y);
            m.z = mishf(norm1 * (ue1.z + ve1.z) + b.z);
            m.w = mishf(norm1 * (ue1.w + ve1.w) + b.w);
            red_add_v4(&Pe[di1], m);
        }
    } else {
        int bid = blockIdx.x - gNE;
        int base = (bid * 8 + (threadIdx.x >> 5)) * 4;
        if (base >= E) return;
        int cnt = min(4, E - base);

        int src[4], dst[4];
        float d2[4];
        #pragma unroll
        for (int q = 0; q < 4; ++q) {
            int e = base + ((q < cnt) ? q : 0);
            src[q] = ei[e];
            dst[q] = ei[E + e];
        }
        #pragma unroll
        for (int q = 0; q < 4; ++q) {
            float dx = coords[src[q] * 3 + 0] - coords[dst[q] * 3 + 0];
            float dy = coords[src[q] * 3 + 1] - coords[dst[q] * 3 + 1];
            float dz = coords[src[q] * 3 + 2] - coords[dst[q] * 3 + 2];
            d2[q] = dx * dx + dy * dy + dz * dz;
        }
        float4 xs[4];
        #pragma unroll
        for (int q = 0; q < 4; ++q)
            xs[q] = x[src[q] * 32 + lane];

        #pragma unroll
        for (int q = 0; q < 4; ++q) {
            if (q >= cnt) break;
            float4 m = make_float4(d2[q] * xs[q].x, d2[q] * xs[q].y,
                                   d2[q] * xs[q].z, d2[q] * xs[q].w);
            red_add_v4(&T[dst[q] * 32 + lane], m);
            if (lane == 0) {
                atomicAdd(&s_arr[dst[q]], d2[q]);
                atomicAdd(&deg_arr[dst[q]], 1.0f);
            }
        }
    }
}

// ---------------------------------------------------------------------------
// Batched / chain-fused mma.sync GEMM (double-buffered B, 104448 B smem,
// 2 CTAs/SM — do NOT force 3; the accumulator spills).
// ---------------------------------------------------------------------------
struct Job {
    const float* A; const float* A2;
    const float* rowScale; const float* bias;
    const float* biasRowScale; const float* Cadd;
    const float* aE1; const float* aE2;
    const float* aF0; const float* aF1; const float* aF2;
    float* C;
    int w1, w2, actMode, convertA, chainOut, attn, bnstat, zeroAcc;
};
struct JobList { Job j[12]; int count; };

__global__ void __launch_bounds__(256, 2) mma_gemm(JobList jl, int n)
{
    extern __shared__ __nv_bfloat16 sm[];
    const int tid  = threadIdx.x;
    const int wid  = tid >> 5;
    const int lane = tid & 31;
    const int tq = lane >> 2;
    const int tr = lane & 3;
    const int warpM = wid >> 2;     // 0..1
    const int warpN = wid & 3;      // 0..3
    const int rowBase = blockIdx.x * 64;

    const uint32_t smBase  = smem_u32(sm);
    const uint32_t aHiAddr = smBase;
    const uint32_t aLoAddr = smBase + 17408;
    const uint32_t bHiAddr = smBase + 34816;
    const uint32_t bLoAddr = smBase + 69632;

    const uint32_t aoff0 = ((warpM * 32 + (lane & 15)) * WPAD + (lane >> 4) * 8) * 2;
    const uint32_t aoff1 = aoff0 + 16 * WPAD * 2;
    const int bRow = warpN * 32 + ((lane >> 4) << 3) + (lane & 7);
    const uint32_t boff0 = (bRow * WPAD + ((lane >> 3) & 1) * 8) * 2;
    const uint32_t boff1 = boff0 + 16 * WPAD * 2;

    for (int ji = 0; ji < jl.count; ++ji) {
        const Job J = jl.j[ji];

        float acc[2][4][4];
        #pragma unroll
        for (int i = 0; i < 2; ++i)
            #pragma unroll
            for (int j = 0; j < 4; ++j)
                #pragma unroll
                for (int q = 0; q < 4; ++q) acc[i][j][q] = 0.0f;

        const int passes = (J.A2 != nullptr) ? 2 : 1;
        for (int p = 0; p < passes; ++p) {
            const float* Ap  = p ? J.A2 : J.A;
            const float* rsp = p ? nullptr : J.rowScale;
            const bool doConv = (p == 1) || (J.convertA != 0);
            const int  w = p ? J.w2 : J.w1;

            __syncthreads();   // previous mainloop / chain writes done

            // --- B prefetch: hi group then lo group ---
            {
                const char* src = (const char*)g_wt[w] + tid * 16;
                uint32_t dst = bHiAddr + tid * 16;
                #pragma unroll
                for (int it = 0; it < 9; ++it)
                    cp_async16(dst + it * 4096, src + it * 4096);
                asm volatile("cp.async.commit_group;" ::: "memory");
                #pragma unroll
                for (int it = 9; it < 17; ++it)
                    cp_async16(dst + it * 4096, src + it * 4096);
                asm volatile("cp.async.commit_group;" ::: "memory");
            }

            // --- A tile: 64x128 -> hi/lo bf16 (overlaps B prefetch) ---
            if (doConv) {
                #pragma unroll
                for (int it = 0; it < 8; ++it) {
                    int idx = tid + (it << 8);
                    int row = idx >> 5;
                    int c4  = idx & 31;
                    int grow = rowBase + row;
                    float4 v = make_float4(0.f, 0.f, 0.f, 0.f);
                    if (grow < n) {
                        int gi = grow * 32 + c4;
                        if (J.attn) {
                            float4 e0 = ((const float4*)Ap)[gi];
                            float4 e1 = ((const float4*)J.aE1)[gi];
                            float4 e2 = ((const float4*)J.aE2)[gi];
                            float4 f0 = ((const float4*)J.aF0)[gi];
                            float4 f1 = ((const float4*)J.aF1)[gi];
                            float4 f2 = ((const float4*)J.aF2)[gi];
                            v.x = att3(e0.x, e1.x, e2.x, f0.x, f1.x, f2.x);
                            v.y = att3(e0.y, e1.y, e2.y, f0.y, f1.y, f2.y);
                            v.z = att3(e0.z, e1.z, e2.z, f0.z, f1.z, f2.z);
                            v.w = att3(e0.w, e1.w, e2.w, f0.w, f1.w, f2.w);
                        } else {
                            v = ((const float4*)Ap)[gi];
                            if (rsp) {
                                float s = __ldg(&rsp[grow]);
                                v.x *= s; v.y *= s; v.z *= s; v.w *= s;
                            }
                        }
                    }
                    __nv_bfloat16 hx = __float2bfloat16(v.x);
                    __nv_bfloat16 hy = __float2bfloat16(v.y);
                    __nv_bfloat16 hz = __float2bfloat16(v.z);
                    __nv_bfloat16 hw = __float2bfloat16(v.w);
                    __nv_bfloat162 h01; h01.x = hx; h01.y = hy;
                    __nv_bfloat162 h23; h23.x = hz; h23.y = hw;
                    __nv_bfloat162 l01, l23;
                    l01.x = __float2bfloat16(v.x - __bfloat162float(hx));
                    l01.y = __float2bfloat16(v.y - __bfloat162float(hy));
                    l23.x = __float2bfloat16(v.z - __bfloat162float(hz));
                    l23.y = __float2bfloat16(v.w - __bfloat162float(hw));
                    int o = row * WPAD + c4 * 4;
                    *(__nv_bfloat162*)&sm[o]            = h01;
                    *(__nv_bfloat162*)&sm[o + 2]        = h23;
                    *(__nv_bfloat162*)&sm[8704 + o]     = l01;
                    *(__nv_bfloat162*)&sm[8704 + o + 2] = l23;
                }
            }
            // B_hi arrived (lo still pending)
            asm volatile("cp.async.wait_group 1;" ::: "memory");
            __syncthreads();

            // --- split terms using B_hi: hi_a·hi_b, lo_a·hi_b ---
            #pragma unroll
            for (int sel = 0; sel < 2; ++sel) {
                const uint32_t aB = (sel == 1) ? aLoAddr : aHiAddr;
                #pragma unroll
                for (int kk = 0; kk < 8; ++kk) {
                    uint32_t ko = kk * 32;
                    uint32_t a0[4], a1[4], b0[4], b1[4];
                    ldsm4(a0, aB + aoff0 + ko);
                    ldsm4(a1, aB + aoff1 + ko);
                    ldsm4(b0, bHiAddr + boff0 + ko);
                    ldsm4(b1, bHiAddr + boff1 + ko);
                    mma_bf16(acc[0][0], a0, &b0[0]);
                    mma_bf16(acc[0][1], a0, &b0[2]);
                    mma_bf16(acc[0][2], a0, &b1[0]);
                    mma_bf16(acc[0][3], a0, &b1[2]);
                    mma_bf16(acc[1][0], a1, &b0[0]);
                    mma_bf16(acc[1][1], a1, &b0[2]);
                    mma_bf16(acc[1][2], a1, &b1[0]);
                    mma_bf16(acc[1][3], a1, &b1[2]);
                }
            }
            // B_lo arrived
            asm volatile("cp.async.wait_group 0;" ::: "memory");
            __syncthreads();

            // --- split term hi_a·lo_b ---
            #pragma unroll
            for (int kk = 0; kk < 8; ++kk) {
                uint32_t ko = kk * 32;
                uint32_t a0[4], a1[4], b0[4], b1[4];
                ldsm4(a0, aHiAddr + aoff0 + ko);
                ldsm4(a1, aHiAddr + aoff1 + ko);
                ldsm4(b0, bLoAddr + boff0 + ko);
                ldsm4(b1, bLoAddr + boff1 + ko);
                mma_bf16(acc[0][0], a0, &b0[0]);
                mma_bf16(acc[0][1], a0, &b0[2]);
                mma_bf16(acc[0][2], a0, &b1[0]);
                mma_bf16(acc[0][3], a0, &b1[2]);
                mma_bf16(acc[1][0], a1, &b0[0]);
                mma_bf16(acc[1][1], a1, &b0[2]);
                mma_bf16(acc[1][2], a1, &b1[0]);
                mma_bf16(acc[1][3], a1, &b1[2]);
            }
        }

        if (J.chainOut) {
            __syncthreads();   // all warps done reading A smem
            #pragma unroll
            for (int mt = 0; mt < 2; ++mt) {
                #pragma unroll
                for (int half = 0; half < 2; ++half) {
                    int rloc = warpM * 32 + mt * 16 + tq + half * 8;
                    #pragma unroll
                    for (int nt = 0; nt < 4; ++nt) {
                        int col = warpN * 32 + nt * 8 + tr * 2;
                        float v0 = acc[mt][nt][half * 2];
                        float v1 = acc[mt][nt][half * 2 + 1];
                        if (J.bias) {
                            v0 += __ldg(&J.bias[col]);
                            v1 += __ldg(&J.bias[col + 1]);
                        }
                        if (J.actMode == 1)      { v0 = mishf(v0); v1 = mishf(v1); }
                        else if (J.actMode == 2) { v0 = mishf(mishf(v0)); v1 = mishf(mishf(v1)); }
                        __nv_bfloat16 h0 = __float2bfloat16(v0);
                        __nv_bfloat16 h1 = __float2bfloat16(v1);
                        __nv_bfloat162 hh; hh.x = h0; hh.y = h1;
                        __nv_bfloat162 ll;
                        ll.x = __float2bfloat16(v0 - __bfloat162float(h0));
                        ll.y = __float2bfloat16(v1 - __bfloat162float(h1));
                        int o = rloc * WPAD + col;
                        *(__nv_bfloat162*)&sm[o]        = hh;
                        *(__nv_bfloat162*)&sm[8704 + o] = ll;
                    }
                }
            }
        } else {
            float* scol = (float*)sm;          // [128] sums, [128] sumsq
            if (J.bnstat) {
                __syncthreads();               // mainloop smem reads done
                if (tid < 256) scol[tid] = 0.0f;
                __syncthreads();
            }
            float cs[8], cq[8];
            #pragma unroll
            for (int q = 0; q < 8; ++q) { cs[q] = 0.f; cq[q] = 0.f; }

            #pragma unroll
            for (int mt = 0; mt < 2; ++mt) {
                #pragma unroll
                for (int half = 0; half < 2; ++half) {
                    int grow = rowBase + warpM * 32 + mt * 16 + tq + half * 8;
                    if (grow >= n) continue;
                    float brs = J.biasRowScale ? __ldg(&J.biasRowScale[grow]) : 1.0f;
                    #pragma unroll
                    for (int nt = 0; nt < 4; ++nt) {
                        int col = warpN * 32 + nt * 8 + tr * 2;
                        float v0 = acc[mt][nt][half * 2];
                        float v1 = acc[mt][nt][half * 2 + 1];
                        if (J.bias) {
                            v0 += __ldg(&J.bias[col])     * brs;
                            v1 += __ldg(&J.bias[col + 1]) * brs;
                        }
                        if (J.Cadd) {
                            float2 ca = *(const float2*)&J.Cadd[grow * 128 + col];
                            v0 += ca.x; v1 += ca.y;
                        }
                        if (J.actMode == 1)      { v0 = mishf(v0); v1 = mishf(v1); }
                        else if (J.actMode == 2) { v0 = mishf(mishf(v0)); v1 = mishf(mishf(v1)); }
                        *(float2*)&J.C[grow * 128 + col] = make_float2(v0, v1);
                        if (J.bnstat) {
                            cs[nt * 2]     += v0; cq[nt * 2]     += v0 * v0;
                            cs[nt * 2 + 1] += v1; cq[nt * 2 + 1] += v1 * v1;
                        }
                    }
                }
            }
            if (J.bnstat) {
                #pragma unroll
                for (int nt = 0; nt < 4; ++nt) {
                    int col = warpN * 32 + nt * 8 + tr * 2;
                    atomicAdd(&scol[col],           cs[nt * 2]);
                    atomicAdd(&scol[col + 1],       cs[nt * 2 + 1]);
                    atomicAdd(&scol[128 + col],     cq[nt * 2]);
                    atomicAdd(&scol[128 + col + 1], cq[nt * 2 + 1]);
                }
                __syncthreads();
                if (tid < 128) {
                    atomicAdd(&g_bnsum[tid], scol[tid]);
                    atomicAdd(&g_bnsq[tid],  scol[128 + tid]);
                }
            }
            if (J.zeroAcc) {
                float4 z = make_float4(0.f, 0.f, 0.f, 0.f);
                #pragma unroll
                for (int it = 0; it < 8; ++it) {
                    int idx = tid + (it << 8);
                    int row = idx >> 5;
                    int c   = idx & 31;
                    int grow = rowBase + row;
                    if (grow < n) {
                        g_b6[grow * 32 + c] = z;
                        g_b7[grow * 32 + c] = z;
                        g_b8[grow * 32 + c] = z;
                    }
                }
                if (tid < 64) {
                    int grow = rowBase + tid;
                    if (grow < n) { g_s[grow] = 0.f; g_deg[grow] = 0.f; }
                }
            }
        }
    }
}

// ---------------------------------------------------------------------------
// Final BN + mish, float4-vectorized (4 columns per thread).
// ---------------------------------------------------------------------------
__global__ void final_kernel(const float4* __restrict__ H,
                             const float4* __restrict__ sum,
                             const float4* __restrict__ sq,
                             const float4* __restrict__ gamma,
                             const float4* __restrict__ beta,
                             float4* __restrict__ out, int n)
{
    int i = blockIdx.x * blockDim.x + threadIdx.x;
    if (i >= n * 32) return;
    int d4 = i & 31;
    float invn = 1.0f / (float)n;
    float4 s = sum[d4], q = sq[d4], g = gamma[d4], b = beta[d4];
    float4 h = H[i];
    float4 o;
    {
        float mean = s.x * invn;
        float var  = q.x * invn - mean * mean;
        o.x = mishf((h.x - mean) * rsqrtf(var + 1e-5f) * g.x + b.x);
    }
    {
        float mean = s.y * invn;
        float var  = q.y * invn - mean * mean;
        o.y = mishf((h.y - mean) * rsqrtf(var + 1e-5f) * g.y + b.y);
    }
    {
        float mean = s.z * invn;
        float var  = q.z * invn - mean * mean;
        o.z = mishf((h.z - mean) * rsqrtf(var + 1e-5f) * g.z + b.z);
    }
    {
        float mean = s.w * invn;
        float var  = q.w * invn - mean * mean;
        o.w = mishf((h.w - mean) * rsqrtf(var + 1e-5f) * g.w + b.w);
    }
    out[i] = o;
}

// ---------------------------------------------------------------------------
// Host launch
// ---------------------------------------------------------------------------
static float* symaddr(const void* sym) {
    void* p = nullptr;
    cudaGetSymbolAddress(&p, sym);
    return (float*)p;
}

#define GEMM_SMEM 104448

static Job mkjob(const float* A, int w1, float* C, int act,
                 const float* bias = nullptr, int convertA = 1,
                 const float* A2 = nullptr, int w2 = -1,
                 const float* rowScale = nullptr,
                 const float* brs = nullptr, const float* Cadd = nullptr,
                 int chainOut = 0)
{
    Job j;
    j.A = A; j.A2 = A2; j.rowScale = rowScale; j.bias = bias;
    j.biasRowScale = brs; j.Cadd = Cadd; j.C = C;
    j.aE1 = nullptr; j.aE2 = nullptr;
    j.aF0 = nullptr; j.aF1 = nullptr; j.aF2 = nullptr;
    j.w1 = w1; j.w2 = w2; j.actMode = act; j.convertA = convertA;
    j.chainOut = chainOut; j.attn = 0; j.bnstat = 0; j.zeroAcc = 0;
    return j;
}

extern "C" void kernel_launch(void* const* d_in, const int* in_sizes, int n_in,
                              void* d_out, int out_size)
{
    const float* x       = (const float*)d_in[0];
    const float* coords  = (const float*)d_in[1];
    const int*   ei      = (const int*)  d_in[2];
    const int*   bt      = (const int*)  d_in[3];
    const float* W_nb    = (const float*)d_in[4];
    const float* b_nb    = (const float*)d_in[5];
    const float* W_nout  = (const float*)d_in[6];
    const float* b_nout  = (const float*)d_in[7];
    const float* conv_w  = (const float*)d_in[8];
    const float* conv_b  = (const float*)d_in[9];
    const float* W_el    = (const float*)d_in[10];
    const float* b_el    = (const float*)d_in[11];
    const float* W_eout  = (const float*)d_in[12];
    const float* b_eout  = (const float*)d_in[13];
    const float* W_coord = (const float*)d_in[14];
    const float* b_coord = (const float*)d_in[15];
    const float* W_pair  = (const float*)d_in[16];
    const float* b_pair  = (const float*)d_in[17];
    const float* W_sout  = (const float*)d_in[18];
    const float* b_sout  = (const float*)d_in[19];
    const float* W_init  = (const float*)d_in[20];
    const float* feat_lin= (const float*)d_in[21];
    const float* W_att   = (const float*)d_in[22];
    const float* W_agg   = (const float*)d_in[23];
    const float* gamma   = (const float*)d_in[24];
    const float* beta    = (const float*)d_in[25];

    const int N = in_sizes[0] / 128;
    const int E = in_sizes[2] / 2;

    static bool attrSet = false;
    if (!attrSet) {
        cudaFuncSetAttribute(mma_gemm,
            cudaFuncAttributeMaxDynamicSharedMemorySize, GEMM_SMEM);
        attrSet = true;
    }

    float* Un    = symaddr(g_b0);
    float* Vn    = symaddr(g_b1);
    float* Ue    = symaddr(g_b2);
    float* Ve    = symaddr(g_b3);
    float* Hagg  = symaddr(g_b4);
    float* Pn    = symaddr(g_b6);
    float* Pe    = symaddr(g_b7);
    float* T     = symaddr(g_b8);
    float* Fn    = symaddr(g_b9);
    float* Fe    = symaddr(g_b10);
    float* Fs    = symaddr(g_b13);
    float* sArr  = symaddr(g_s);
    float* dArr  = symaddr(g_deg);
    float* bnS   = symaddr(g_bnsum);
    float* bnQ   = symaddr(g_bnsq);
    float* E0 = Un; float* E1 = Vn; float* E2 = Ue;

    cudaMemsetAsync(bnS, 0, 128 * sizeof(float));
    cudaMemsetAsync(bnQ, 0, 128 * sizeof(float));

    // Weight indices in g_wt:
    //  0 Wnb_top  1 Wnb_bot  2 Wel_top  3 Wel_bot  4 W_init(unused)
    //  5 Watt_top(unused)  6 W_nout  7 W_eout  8 Wc_top  9 Wc_bot
    // 10 W_pair 11 Ws_top 12 Ws_bot 13 fl0 14 fl1 15 fl2 16 Watt_bot 17 W_agg
    WPtrs wp;
    wp.p[0]  = W_nb;               wp.p[1]  = W_nb + 128 * 128;
    wp.p[2]  = W_el;               wp.p[3]  = W_el + 128 * 128;
    wp.p[4]  = W_init;             wp.p[5]  = W_att;
    wp.p[6]  = W_nout;             wp.p[7]  = W_eout;
    wp.p[8]  = W_coord;            wp.p[9]  = W_coord + 128 * 128;
    wp.p[10] = W_pair;             wp.p[11] = W_sout;
    wp.p[12] = W_sout + 128 * 128; wp.p[13] = feat_lin;
    wp.p[14] = feat_lin + 128 * 128; wp.p[15] = feat_lin + 2 * 128 * 128;
    wp.p[16] = W_att + 128 * 128;  wp.p[17] = W_agg;

    setup_weights<<<dim3(18, 8), 256>>>(wp);

    dim3 gb(256);
    dim3 gg((N + 63) / 64);

    JobList jl;

    // --- L1: 4 projections, sharing A=x (convert once); job0 also zeroes
    //     Pn/Pe/T/s/deg rows.  (Hini/Einit eliminated: the lin_init@W_att_top
    //     logit term is constant across the softmax path axis and cancels.) ---
    jl.count = 4;
    jl.j[0] = mkjob(x, 0, Un,   0, b_nb, 1);
    jl.j[0].zeroAcc = 1;
    jl.j[1] = mkjob(x, 1, Vn,   0, nullptr, 0);
    jl.j[2] = mkjob(x, 2, Ue,   0, nullptr, 0);
    jl.j[3] = mkjob(x, 3, Ve,   0, nullptr, 0);
    mma_gemm<<<gg, gb, GEMM_SMEM>>>(jl, N);

    // --- edge phase: ONE fused launch, ne-blocks + struct-blocks co-resident ---
    int gNE = (E + 15) / 16;
    int gST = (E + 31) / 32;
    edge_fused<<<gNE + gST, 256>>>(ei, bt, conv_w, conv_b, b_el, coords,
                                   (const float4*)x,
                                   (const float4*)Un, (const float4*)Vn,
                                   (const float4*)Ue, (const float4*)Ve,
                                   (float4*)Pn, (float4*)Pe, (float4*)T,
                                   sArr, dArr, E, gNE);

    // --- L2+L3 merged (all row deps are CTA-local):
    //     Fn, Fe, Qp(chain)->Q(chain)->Fs, per-path HR chains -> E_f (no
    //     Einit offset needed), fused-attention Hagg + BN stats ---
    jl.count = 12;
    jl.j[0]  = mkjob(Pn, 6, Fn, 1, b_nout, 1);
    jl.j[1]  = mkjob(Pe, 7, Fe, 1, b_eout, 1);
    jl.j[2]  = mkjob(x, 8, nullptr, 0, b_coord, 1, T, 9, sArr, dArr, nullptr, 1);
    jl.j[3]  = mkjob(nullptr, 10, nullptr, 1, b_pair, 0, nullptr, -1, nullptr, nullptr, nullptr, 1);
    jl.j[4]  = mkjob(x, 12, Fs, 1, b_sout, 0, x, 11);
    jl.j[5]  = mkjob(Fn, 13, nullptr, 2, nullptr, 1, nullptr, -1, nullptr, nullptr, nullptr, 1);
    jl.j[6]  = mkjob(x, 16, E0, 0, nullptr, 0);
    jl.j[7]  = mkjob(Fe, 14, nullptr, 2, nullptr, 1, nullptr, -1, nullptr, nullptr, nullptr, 1);
    jl.j[8]  = mkjob(x, 16, E1, 0, nullptr, 0);
    jl.j[9]  = mkjob(Fs, 15, nullptr, 2, nullptr, 1, nullptr, -1, nullptr, nullptr, nullptr, 1);
    jl.j[10] = mkjob(x, 16, E2, 0, nullptr, 0);
    jl.j[11] = mkjob(E0, 17, Hagg, 0);
    jl.j[11].attn = 1; jl.j[11].bnstat = 1;
    jl.j[11].aE1 = E1; jl.j[11].aE2 = E2;
    jl.j[11].aF0 = Fn; jl.j[11].aF1 = Fe; jl.j[11].aF2 = Fs;
    mma_gemm<<<gg, gb, GEMM_SMEM>>>(jl, N);

    final_kernel<<<(N * 32 + 255) / 256, 256>>>(
        (const float4*)Hagg, (const float4*)bnS, (const float4*)bnQ,
        (const float4*)gamma, (const float4*)beta, (float4*)d_out, N);
}

// round 16
// speedup vs baseline: 1.7251x; 1.0194x over previous
#include <cuda_runtime.h>
#include <cuda_bf16.h>
#include <cstdint>

// ---------------------------------------------------------------------------
// MultiPathLayer: N=50000 nodes, E=800000 edges, D=128.
// GEMMs via mma.sync bf16 (split-bf16, fp32 accuracy), ldmatrix, cp.async
// with CROSS-PASS B pipelining (next pass's B_hi prefetched during current
// mainloop-lo). 104KB smem, 2 CTAs/SM (3 spills the accumulator).
// Einit/Hini eliminated (softmax shift invariance). Smem chain-fusion,
// fused attention + BN stats + accumulator zeroing; fused edge launch.
// ---------------------------------------------------------------------------

#define NMAX 50000
#define DDIM 128
#define WPAD 136           // padded row length in bf16 elems — LDSM conflict-free
#define WELEMS (128 * WPAD)

__device__ float4 g_b0 [NMAX * 32];   // Un   -> later E0
__device__ float4 g_b1 [NMAX * 32];   // Vn   -> later E1
__device__ float4 g_b2 [NMAX * 32];   // Ue   -> later E2
__device__ float4 g_b3 [NMAX * 32];   // Ve
__device__ float4 g_b4 [NMAX * 32];   // Hagg
__device__ float4 g_b6 [NMAX * 32];   // Pn
__device__ float4 g_b7 [NMAX * 32];   // Pe
__device__ float4 g_b8 [NMAX * 32];   // T
__device__ float4 g_b9 [NMAX * 32];   // Fn
__device__ float4 g_b10[NMAX * 32];   // Fe
__device__ float4 g_b13[NMAX * 32];   // Fs
__device__ float  g_s[NMAX];
__device__ float  g_deg[NMAX];
__device__ float  g_bnsum[DDIM];
__device__ float  g_bnsq[DDIM];

// Pre-converted weights: [weight][hi/lo][n*WPAD + k] (B operand layout [n][k]).
__device__ __align__(16) __nv_bfloat16 g_wt[18][2][WELEMS];

__device__ __forceinline__ float mishf(float x) {
    float e  = __expf(fminf(x, 30.0f));
    float t  = 1.0f + e;
    float t2 = t * t;
    return x * __fdividef(t2 - 1.0f, t2 + 1.0f);
}

__device__ __forceinline__ void red_add_v4(float4* p, float4 v) {
    asm volatile("red.global.add.v4.f32 [%0], {%1,%2,%3,%4};"
                 :: "l"(p), "f"(v.x), "f"(v.y), "f"(v.z), "f"(v.w)
                 : "memory");
}

__device__ __forceinline__ uint32_t smem_u32(const void* p) {
    uint32_t a;
    asm("{ .reg .u64 t; cvta.to.shared.u64 t, %1; cvt.u32.u64 %0, t; }"
        : "=r"(a) : "l"(p));
    return a;
}

__device__ __forceinline__ void mma_bf16(float* c, const uint32_t* a,
                                         const uint32_t* b) {
    asm volatile(
        "mma.sync.aligned.m16n8k16.row.col.f32.bf16.bf16.f32 "
        "{%0,%1,%2,%3}, {%4,%5,%6,%7}, {%8,%9}, {%0,%1,%2,%3};"
        : "+f"(c[0]), "+f"(c[1]), "+f"(c[2]), "+f"(c[3])
        : "r"(a[0]), "r"(a[1]), "r"(a[2]), "r"(a[3]), "r"(b[0]), "r"(b[1]));
}

__device__ __forceinline__ void ldsm4(uint32_t* r, uint32_t addr) {
    asm volatile("ldmatrix.sync.aligned.m8n8.x4.shared.b16 {%0,%1,%2,%3}, [%4];"
        : "=r"(r[0]), "=r"(r[1]), "=r"(r[2]), "=r"(r[3]) : "r"(addr));
}

__device__ __forceinline__ void cp_async16(uint32_t saddr, const void* g) {
    asm volatile("cp.async.cg.shared.global [%0], [%1], 16;"
                 :: "r"(saddr), "l"(g) : "memory");
}

// prefetch one 34816-byte half (hi or lo) of weight w into smem buffer
__device__ __forceinline__ void prefetch_half(uint32_t dstAddr,
                                              const __nv_bfloat16* src_w,
                                              int tid) {
    const char* src = (const char*)src_w + tid * 16;
    uint32_t dst = dstAddr + tid * 16;
    #pragma unroll
    for (int it = 0; it < 8; ++it)
        cp_async16(dst + it * 4096, src + it * 4096);
    if (tid < 128) cp_async16(dst + 8 * 4096, src + 8 * 4096);
    asm volatile("cp.async.commit_group;" ::: "memory");
}

// softmax over 3 logits, weighted sum of 3 features (scalar)
__device__ __forceinline__ float att3(float e0, float e1, float e2,
                                      float f0, float f1, float f2) {
    float m = fmaxf(e0, fmaxf(e1, e2));
    float p0 = __expf(e0 - m), p1 = __expf(e1 - m), p2 = __expf(e2 - m);
    return __fdividef(p0 * f0 + p1 * f1 + p2 * f2, p0 + p1 + p2);
}

// ---------------------------------------------------------------------------
// Weight setup.
// ---------------------------------------------------------------------------
struct WPtrs { const float* p[18]; };

__global__ void setup_weights(WPtrs wp)
{
    int w = blockIdx.x;
    const float* W = wp.p[w];
    __nv_bfloat16* hi = g_wt[w][0];
    __nv_bfloat16* lo = g_wt[w][1];
    for (int it = 0; it < 8; ++it) {
        int idx = blockIdx.y * 2048 + it * 256 + threadIdx.x;
        int k = idx >> 7;
        int n = idx & 127;
        float v = W[idx];
        __nv_bfloat16 h = __float2bfloat16(v);
        __nv_bfloat16 l = __float2bfloat16(v - __bfloat162float(h));
        hi[n * WPAD + k] = h;
        lo[n * WPAD + k] = l;
    }
}

// ---------------------------------------------------------------------------
// Fused edge phase: blocks [0, gNE) do node+edge paths (2 edges/warp),
// blocks [gNE, ...) do struct path (4 edges/warp).
// ---------------------------------------------------------------------------
__global__ void __launch_bounds__(256) edge_fused(
    const int*   __restrict__ ei,
    const int*   __restrict__ bt,
    const float* __restrict__ conv_w,
    const float* __restrict__ conv_b,
    const float* __restrict__ b_el,
    const float* __restrict__ coords,
    const float4* __restrict__ x,
    const float4* __restrict__ Un, const float4* __restrict__ Vn,
    const float4* __restrict__ Ue, const float4* __restrict__ Ve,
    float4* Pn, float4* Pe, float4* T,
    float* s_arr, float* deg_arr, int E, int gNE)
{
    int lane = threadIdx.x & 31;

    if ((int)blockIdx.x < gNE) {
        int base = (blockIdx.x * 8 + (threadIdx.x >> 5)) * 2;
        if (base >= E) return;
        int e1ok = (base + 1 < E);

        int src0 = ei[base];
        int dst0 = ei[E + base];
        int src1 = e1ok ? ei[base + 1]     : src0;
        int dst1 = e1ok ? ei[E + base + 1] : dst0;
        float norm0 = conv_w[bt[base]] + conv_b[0];
        float norm1 = conv_w[bt[e1ok ? base + 1 : base]] + conv_b[0];

        int di0 = dst0 * 32 + lane, si0 = src0 * 32 + lane;
        int di1 = dst1 * 32 + lane, si1 = src1 * 32 + lane;

        float4 un0 = Un[di0];
        float4 vn0 = Vn[si0];
        float4 ue0 = Ue[di0];
        float4 ve0 = Ve[si0];
        float4 un1 = Un[di1];
        float4 vn1 = Vn[si1];
        float4 ue1 = Ue[di1];
        float4 ve1 = Ve[si1];
        float4 b   = ((const float4*)b_el)[lane];

        float4 m;
        m.x = mishf(un0.x + vn0.x); m.y = mishf(un0.y + vn0.y);
        m.z = mishf(un0.z + vn0.z); m.w = mishf(un0.w + vn0.w);
        red_add_v4(&Pn[di0], m);

        m.x = mishf(norm0 * (ue0.x + ve0.x) + b.x);
        m.y = mishf(norm0 * (ue0.y + ve0.y) + b.y);
        m.z = mishf(norm0 * (ue0.z + ve0.z) + b.z);
        m.w = mishf(norm0 * (ue0.w + ve0.w) + b.w);
        red_add_v4(&Pe[di0], m);

        if (e1ok) {
            m.x = mishf(un1.x + vn1.x); m.y = mishf(un1.y + vn1.y);
            m.z = mishf(un1.z + vn1.z); m.w = mishf(un1.w + vn1.w);
            red_add_v4(&Pn[di1], m);

            m.x = mishf(norm1 * (ue1.x + ve1.x) + b.x);
            m.y = mishf(norm1 * (ue1.y + ve1.y) + b.y);
            m.z = mishf(norm1 * (ue1.z + ve1.z) + b.z);
            m.w = mishf(norm1 * (ue1.w + ve1.w) + b.w);
            red_add_v4(&Pe[di1], m);
        }
    } else {
        int bid = blockIdx.x - gNE;
        int base = (bid * 8 + (threadIdx.x >> 5)) * 4;
        if (base >= E) return;
        int cnt = min(4, E - base);

        int src[4], dst[4];
        float d2[4];
        #pragma unroll
        for (int q = 0; q < 4; ++q) {
            int e = base + ((q < cnt) ? q : 0);
            src[q] = ei[e];
            dst[q] = ei[E + e];
        }
        #pragma unroll
        for (int q = 0; q < 4; ++q) {
            float dx = coords[src[q] * 3 + 0] - coords[dst[q] * 3 + 0];
            float dy = coords[src[q] * 3 + 1] - coords[dst[q] * 3 + 1];
            float dz = coords[src[q] * 3 + 2] - coords[dst[q] * 3 + 2];
            d2[q] = dx * dx + dy * dy + dz * dz;
        }
        float4 xs[4];
        #pragma unroll
        for (int q = 0; q < 4; ++q)
            xs[q] = x[src[q] * 32 + lane];

        #pragma unroll
        for (int q = 0; q < 4; ++q) {
            if (q >= cnt) break;
            float4 m = make_float4(d2[q] * xs[q].x, d2[q] * xs[q].y,
                                   d2[q] * xs[q].z, d2[q] * xs[q].w);
            red_add_v4(&T[dst[q] * 32 + lane], m);
            if (lane == 0) {
                atomicAdd(&s_arr[dst[q]], d2[q]);
                atomicAdd(&deg_arr[dst[q]], 1.0f);
            }
        }
    }
}

// ---------------------------------------------------------------------------
// Batched / chain-fused mma.sync GEMM with cross-pass B pipelining.
// Pending cp.async groups at pass start: {Bhi_this}. Then +Blo_this;
// wait_group 1 -> Bhi done; after mainloop-hi, wait_group 0 -> Blo done;
// issue Bhi_next (overlaps mainloop-lo + epilogue + next conversion).
// ---------------------------------------------------------------------------
struct Job {
    const float* A; const float* A2;
    const float* rowScale; const float* bias;
    const float* biasRowScale; const float* Cadd;
    const float* aE1; const float* aE2;
    const float* aF0; const float* aF1; const float* aF2;
    float* C;
    int w1, w2, actMode, convertA, chainOut, attn, bnstat, zeroAcc;
};
struct JobList { Job j[12]; int count; };

__global__ void __launch_bounds__(256, 2) mma_gemm(JobList jl, int n)
{
    extern __shared__ __nv_bfloat16 sm[];
    const int tid  = threadIdx.x;
    const int wid  = tid >> 5;
    const int lane = tid & 31;
    const int tq = lane >> 2;
    const int tr = lane & 3;
    const int warpM = wid >> 2;     // 0..1
    const int warpN = wid & 3;      // 0..3
    const int rowBase = blockIdx.x * 64;

    const uint32_t smBase  = smem_u32(sm);
    const uint32_t aHiAddr = smBase;
    const uint32_t aLoAddr = smBase + 17408;
    const uint32_t bHiAddr = smBase + 34816;
    const uint32_t bLoAddr = smBase + 69632;

    const uint32_t aoff0 = ((warpM * 32 + (lane & 15)) * WPAD + (lane >> 4) * 8) * 2;
    const uint32_t aoff1 = aoff0 + 16 * WPAD * 2;
    const int bRow = warpN * 32 + ((lane >> 4) << 3) + (lane & 7);
    const uint32_t boff0 = (bRow * WPAD + ((lane >> 3) & 1) * 8) * 2;
    const uint32_t boff1 = boff0 + 16 * WPAD * 2;

    // prime the pipeline: first pass's B_hi
    prefetch_half(bHiAddr, g_wt[jl.j[0].w1][0], tid);

    for (int ji = 0; ji < jl.count; ++ji) {
        const Job J = jl.j[ji];

        float acc[2][4][4];
        #pragma unroll
        for (int i = 0; i < 2; ++i)
            #pragma unroll
            for (int j = 0; j < 4; ++j)
                #pragma unroll
                for (int q = 0; q < 4; ++q) acc[i][j][q] = 0.0f;

        const int passes = (J.A2 != nullptr) ? 2 : 1;
        for (int p = 0; p < passes; ++p) {
            const float* Ap  = p ? J.A2 : J.A;
            const float* rsp = p ? nullptr : J.rowScale;
            const bool doConv = (p == 1) || (J.convertA != 0);
            const int  w = p ? J.w2 : J.w1;

            __syncthreads();   // previous mainloop-lo / chain writes done

            // --- B_lo prefetch for this pass (B_hi already in flight) ---
            prefetch_half(bLoAddr, g_wt[w][1], tid);

            // --- A tile: 64x128 -> hi/lo bf16 (overlaps B transfers) ---
            if (doConv) {
                #pragma unroll
                for (int it = 0; it < 8; ++it) {
                    int idx = tid + (it << 8);
                    int row = idx >> 5;
                    int c4  = idx & 31;
                    int grow = rowBase + row;
                    float4 v = make_float4(0.f, 0.f, 0.f, 0.f);
                    if (grow < n) {
                        int gi = grow * 32 + c4;
                        if (J.attn) {
                            float4 e0 = ((const float4*)Ap)[gi];
                            float4 e1 = ((const float4*)J.aE1)[gi];
                            float4 e2 = ((const float4*)J.aE2)[gi];
                            float4 f0 = ((const float4*)J.aF0)[gi];
                            float4 f1 = ((const float4*)J.aF1)[gi];
                            float4 f2 = ((const float4*)J.aF2)[gi];
                            v.x = att3(e0.x, e1.x, e2.x, f0.x, f1.x, f2.x);
                            v.y = att3(e0.y, e1.y, e2.y, f0.y, f1.y, f2.y);
                            v.z = att3(e0.z, e1.z, e2.z, f0.z, f1.z, f2.z);
                            v.w = att3(e0.w, e1.w, e2.w, f0.w, f1.w, f2.w);
                        } else {
                            v = ((const float4*)Ap)[gi];
                            if (rsp) {
                                float s = __ldg(&rsp[grow]);
                                v.x *= s; v.y *= s; v.z *= s; v.w *= s;
                            }
                        }
                    }
                    __nv_bfloat16 hx = __float2bfloat16(v.x);
                    __nv_bfloat16 hy = __float2bfloat16(v.y);
                    __nv_bfloat16 hz = __float2bfloat16(v.z);
                    __nv_bfloat16 hw = __float2bfloat16(v.w);
                    __nv_bfloat162 h01; h01.x = hx; h01.y = hy;
                    __nv_bfloat162 h23; h23.x = hz; h23.y = hw;
                    __nv_bfloat162 l01, l23;
                    l01.x = __float2bfloat16(v.x - __bfloat162float(hx));
                    l01.y = __float2bfloat16(v.y - __bfloat162float(hy));
                    l23.x = __float2bfloat16(v.z - __bfloat162float(hz));
                    l23.y = __float2bfloat16(v.w - __bfloat162float(hw));
                    int o = row * WPAD + c4 * 4;
                    *(__nv_bfloat162*)&sm[o]            = h01;
                    *(__nv_bfloat162*)&sm[o + 2]        = h23;
                    *(__nv_bfloat162*)&sm[8704 + o]     = l01;
                    *(__nv_bfloat162*)&sm[8704 + o + 2] = l23;
                }
            }
            // B_hi arrived (B_lo still pending)
            asm volatile("cp.async.wait_group 1;" ::: "memory");
            __syncthreads();

            // --- split terms using B_hi: hi_a·hi_b, lo_a·hi_b ---
            #pragma unroll
            for (int sel = 0; sel < 2; ++sel) {
                const uint32_t aB = (sel == 1) ? aLoAddr : aHiAddr;
                #pragma unroll
                for (int kk = 0; kk < 8; ++kk) {
                    uint32_t ko = kk * 32;
                    uint32_t a0[4], a1[4], b0[4], b1[4];
                    ldsm4(a0, aB + aoff0 + ko);
                    ldsm4(a1, aB + aoff1 + ko);
                    ldsm4(b0, bHiAddr + boff0 + ko);
                    ldsm4(b1, bHiAddr + boff1 + ko);
                    mma_bf16(acc[0][0], a0, &b0[0]);
                    mma_bf16(acc[0][1], a0, &b0[2]);
                    mma_bf16(acc[0][2], a0, &b1[0]);
                    mma_bf16(acc[0][3], a0, &b1[2]);
                    mma_bf16(acc[1][0], a1, &b0[0]);
                    mma_bf16(acc[1][1], a1, &b0[2]);
                    mma_bf16(acc[1][2], a1, &b1[0]);
                    mma_bf16(acc[1][3], a1, &b1[2]);
                }
            }
            // B_lo arrived; all warps done reading B_hi
            asm volatile("cp.async.wait_group 0;" ::: "memory");
            __syncthreads();

            // --- issue NEXT pass's B_hi (overlaps mainloop-lo + epilogue) ---
            {
                int wn = -1;
                if (p + 1 < passes)            wn = J.w2;
                else if (ji + 1 < jl.count)    wn = jl.j[ji + 1].w1;
                if (wn >= 0)
                    prefetch_half(bHiAddr, g_wt[wn][0], tid);
            }

            // --- split term hi_a·lo_b ---
            #pragma unroll
            for (int kk = 0; kk < 8; ++kk) {
                uint32_t ko = kk * 32;
                uint32_t a0[4], a1[4], b0[4], b1[4];
                ldsm4(a0, aHiAddr + aoff0 + ko);
                ldsm4(a1, aHiAddr + aoff1 + ko);
                ldsm4(b0, bLoAddr + boff0 + ko);
                ldsm4(b1, bLoAddr + boff1 + ko);
                mma_bf16(acc[0][0], a0, &b0[0]);
                mma_bf16(acc[0][1], a0, &b0[2]);
                mma_bf16(acc[0][2], a0, &b1[0]);
                mma_bf16(acc[0][3], a0, &b1[2]);
                mma_bf16(acc[1][0], a1, &b0[0]);
                mma_bf16(acc[1][1], a1, &b0[2]);
                mma_bf16(acc[1][2], a1, &b1[0]);
                mma_bf16(acc[1][3], a1, &b1[2]);
            }
        }

        if (J.chainOut) {
            __syncthreads();   // all warps done reading A smem
            #pragma unroll
            for (int mt = 0; mt < 2; ++mt) {
                #pragma unroll
                for (int half = 0; half < 2; ++half) {
                    int rloc = warpM * 32 + mt * 16 + tq + half * 8;
                    #pragma unroll
                    for (int nt = 0; nt < 4; ++nt) {
                        int col = warpN * 32 + nt * 8 + tr * 2;
                        float v0 = acc[mt][nt][half * 2];
                        float v1 = acc[mt][nt][half * 2 + 1];
                        if (J.bias) {
                            v0 += __ldg(&J.bias[col]);
                            v1 += __ldg(&J.bias[col + 1]);
                        }
                        if (J.actMode == 1)      { v0 = mishf(v0); v1 = mishf(v1); }
                        else if (J.actMode == 2) { v0 = mishf(mishf(v0)); v1 = mishf(mishf(v1)); }
                        __nv_bfloat16 h0 = __float2bfloat16(v0);
                        __nv_bfloat16 h1 = __float2bfloat16(v1);
                        __nv_bfloat162 hh; hh.x = h0; hh.y = h1;
                        __nv_bfloat162 ll;
                        ll.x = __float2bfloat16(v0 - __bfloat162float(h0));
                        ll.y = __float2bfloat16(v1 - __bfloat162float(h1));
                        int o = rloc * WPAD + col;
                        *(__nv_bfloat162*)&sm[o]        = hh;
                        *(__nv_bfloat162*)&sm[8704 + o] = ll;
                    }
                }
            }
        } else {
            float* scol = (float*)sm;          // [128] sums, [128] sumsq
            if (J.bnstat) {
                __syncthreads();               // mainloop smem reads done
                if (tid < 256) scol[tid] = 0.0f;
                __syncthreads();
            }
            float cs[8], cq[8];
            #pragma unroll
            for (int q = 0; q < 8; ++q) { cs[q] = 0.f; cq[q] = 0.f; }

            #pragma unroll
            for (int mt = 0; mt < 2; ++mt) {
                #pragma unroll
                for (int half = 0; half < 2; ++half) {
                    int grow = rowBase + warpM * 32 + mt * 16 + tq + half * 8;
                    if (grow >= n) continue;
                    float brs = J.biasRowScale ? __ldg(&J.biasRowScale[grow]) : 1.0f;
                    #pragma unroll
                    for (int nt = 0; nt < 4; ++nt) {
                        int col = warpN * 32 + nt * 8 + tr * 2;
                        float v0 = acc[mt][nt][half * 2];
                        float v1 = acc[mt][nt][half * 2 + 1];
                        if (J.bias) {
                            v0 += __ldg(&J.bias[col])     * brs;
                            v1 += __ldg(&J.bias[col + 1]) * brs;
                        }
                        if (J.Cadd) {
                            float2 ca = *(const float2*)&J.Cadd[grow * 128 + col];
                            v0 += ca.x; v1 += ca.y;
                        }
                        if (J.actMode == 1)      { v0 = mishf(v0); v1 = mishf(v1); }
                        else if (J.actMode == 2) { v0 = mishf(mishf(v0)); v1 = mishf(mishf(v1)); }
                        *(float2*)&J.C[grow * 128 + col] = make_float2(v0, v1);
                        if (J.bnstat) {
                            cs[nt * 2]     += v0; cq[nt * 2]     += v0 * v0;
                            cs[nt * 2 + 1] += v1; cq[nt * 2 + 1] += v1 * v1;
                        }
                    }
                }
            }
            if (J.bnstat) {
                #pragma unroll
                for (int nt = 0; nt < 4; ++nt) {
                    int col = warpN * 32 + nt * 8 + tr * 2;
                    atomicAdd(&scol[col],           cs[nt * 2]);
                    atomicAdd(&scol[col + 1],       cs[nt * 2 + 1]);
                    atomicAdd(&scol[128 + col],     cq[nt * 2]);
                    atomicAdd(&scol[128 + col + 1], cq[nt * 2 + 1]);
                }
                __syncthreads();
                if (tid < 128) {
                    atomicAdd(&g_bnsum[tid], scol[tid]);
                    atomicAdd(&g_bnsq[tid],  scol[128 + tid]);
                }
            }
            if (J.zeroAcc) {
                float4 z = make_float4(0.f, 0.f, 0.f, 0.f);
                #pragma unroll
                for (int it = 0; it < 8; ++it) {
                    int idx = tid + (it << 8);
                    int row = idx >> 5;
                    int c   = idx & 31;
                    int grow = rowBase + row;
                    if (grow < n) {
                        g_b6[grow * 32 + c] = z;
                        g_b7[grow * 32 + c] = z;
                        g_b8[grow * 32 + c] = z;
                    }
                }
                if (tid < 64) {
                    int grow = rowBase + tid;
                    if (grow < n) { g_s[grow] = 0.f; g_deg[grow] = 0.f; }
                }
            }
        }
    }
}

// ---------------------------------------------------------------------------
// Final BN + mish, float4-vectorized (4 columns per thread).
// ---------------------------------------------------------------------------
__global__ void final_kernel(const float4* __restrict__ H,
                             const float4* __restrict__ sum,
                             const float4* __restrict__ sq,
                             const float4* __restrict__ gamma,
                             const float4* __restrict__ beta,
                             float4* __restrict__ out, int n)
{
    int i = blockIdx.x * blockDim.x + threadIdx.x;
    if (i >= n * 32) return;
    int d4 = i & 31;
    float invn = 1.0f / (float)n;
    float4 s = sum[d4], q = sq[d4], g = gamma[d4], b = beta[d4];
    float4 h = H[i];
    float4 o;
    {
        float mean = s.x * invn;
        float var  = q.x * invn - mean * mean;
        o.x = mishf((h.x - mean) * rsqrtf(var + 1e-5f) * g.x + b.x);
    }
    {
        float mean = s.y * invn;
        float var  = q.y * invn - mean * mean;
        o.y = mishf((h.y - mean) * rsqrtf(var + 1e-5f) * g.y + b.y);
    }
    {
        float mean = s.z * invn;
        float var  = q.z * invn - mean * mean;
        o.z = mishf((h.z - mean) * rsqrtf(var + 1e-5f) * g.z + b.z);
    }
    {
        float mean = s.w * invn;
        float var  = q.w * invn - mean * mean;
        o.w = mishf((h.w - mean) * rsqrtf(var + 1e-5f) * g.w + b.w);
    }
    out[i] = o;
}

// ---------------------------------------------------------------------------
// Host launch
// ---------------------------------------------------------------------------
static float* symaddr(const void* sym) {
    void* p = nullptr;
    cudaGetSymbolAddress(&p, sym);
    return (float*)p;
}

#define GEMM_SMEM 104448

static Job mkjob(const float* A, int w1, float* C, int act,
                 const float* bias = nullptr, int convertA = 1,
                 const float* A2 = nullptr, int w2 = -1,
                 const float* rowScale = nullptr,
                 const float* brs = nullptr, const float* Cadd = nullptr,
                 int chainOut = 0)
{
    Job j;
    j.A = A; j.A2 = A2; j.rowScale = rowScale; j.bias = bias;
    j.biasRowScale = brs; j.Cadd = Cadd; j.C = C;
    j.aE1 = nullptr; j.aE2 = nullptr;
    j.aF0 = nullptr; j.aF1 = nullptr; j.aF2 = nullptr;
    j.w1 = w1; j.w2 = w2; j.actMode = act; j.convertA = convertA;
    j.chainOut = chainOut; j.attn = 0; j.bnstat = 0; j.zeroAcc = 0;
    return j;
}

extern "C" void kernel_launch(void* const* d_in, const int* in_sizes, int n_in,
                              void* d_out, int out_size)
{
    const float* x       = (const float*)d_in[0];
    const float* coords  = (const float*)d_in[1];
    const int*   ei      = (const int*)  d_in[2];
    const int*   bt      = (const int*)  d_in[3];
    const float* W_nb    = (const float*)d_in[4];
    const float* b_nb    = (const float*)d_in[5];
    const float* W_nout  = (const float*)d_in[6];
    const float* b_nout  = (const float*)d_in[7];
    const float* conv_w  = (const float*)d_in[8];
    const float* conv_b  = (const float*)d_in[9];
    const float* W_el    = (const float*)d_in[10];
    const float* b_el    = (const float*)d_in[11];
    const float* W_eout  = (const float*)d_in[12];
    const float* b_eout  = (const float*)d_in[13];
    const float* W_coord = (const float*)d_in[14];
    const float* b_coord = (const float*)d_in[15];
    const float* W_pair  = (const float*)d_in[16];
    const float* b_pair  = (const float*)d_in[17];
    const float* W_sout  = (const float*)d_in[18];
    const float* b_sout  = (const float*)d_in[19];
    const float* W_init  = (const float*)d_in[20];
    const float* feat_lin= (const float*)d_in[21];
    const float* W_att   = (const float*)d_in[22];
    const float* W_agg   = (const float*)d_in[23];
    const float* gamma   = (const float*)d_in[24];
    const float* beta    = (const float*)d_in[25];

    const int N = in_sizes[0] / 128;
    const int E = in_sizes[2] / 2;

    static bool attrSet = false;
    if (!attrSet) {
        cudaFuncSetAttribute(mma_gemm,
            cudaFuncAttributeMaxDynamicSharedMemorySize, GEMM_SMEM);
        attrSet = true;
    }

    float* Un    = symaddr(g_b0);
    float* Vn    = symaddr(g_b1);
    float* Ue    = symaddr(g_b2);
    float* Ve    = symaddr(g_b3);
    float* Hagg  = symaddr(g_b4);
    float* Pn    = symaddr(g_b6);
    float* Pe    = symaddr(g_b7);
    float* T     = symaddr(g_b8);
    float* Fn    = symaddr(g_b9);
    float* Fe    = symaddr(g_b10);
    float* Fs    = symaddr(g_b13);
    float* sArr  = symaddr(g_s);
    float* dArr  = symaddr(g_deg);
    float* bnS   = symaddr(g_bnsum);
    float* bnQ   = symaddr(g_bnsq);
    float* E0 = Un; float* E1 = Vn; float* E2 = Ue;

    cudaMemsetAsync(bnS, 0, 128 * sizeof(float));
    cudaMemsetAsync(bnQ, 0, 128 * sizeof(float));

    // Weight indices in g_wt:
    //  0 Wnb_top  1 Wnb_bot  2 Wel_top  3 Wel_bot  4 W_init(unused)
    //  5 Watt_top(unused)  6 W_nout  7 W_eout  8 Wc_top  9 Wc_bot
    // 10 W_pair 11 Ws_top 12 Ws_bot 13 fl0 14 fl1 15 fl2 16 Watt_bot 17 W_agg
    WPtrs wp;
    wp.p[0]  = W_nb;               wp.p[1]  = W_nb + 128 * 128;
    wp.p[2]  = W_el;               wp.p[3]  = W_el + 128 * 128;
    wp.p[4]  = W_init;             wp.p[5]  = W_att;
    wp.p[6]  = W_nout;             wp.p[7]  = W_eout;
    wp.p[8]  = W_coord;            wp.p[9]  = W_coord + 128 * 128;
    wp.p[10] = W_pair;             wp.p[11] = W_sout;
    wp.p[12] = W_sout + 128 * 128; wp.p[13] = feat_lin;
    wp.p[14] = feat_lin + 128 * 128; wp.p[15] = feat_lin + 2 * 128 * 128;
    wp.p[16] = W_att + 128 * 128;  wp.p[17] = W_agg;

    setup_weights<<<dim3(18, 8), 256>>>(wp);

    dim3 gb(256);
    dim3 gg((N + 63) / 64);

    JobList jl;

    // --- L1: 4 projections, sharing A=x (convert once); job0 also zeroes
    //     Pn/Pe/T/s/deg rows. ---
    jl.count = 4;
    jl.j[0] = mkjob(x, 0, Un,   0, b_nb, 1);
    jl.j[0].zeroAcc = 1;
    jl.j[1] = mkjob(x, 1, Vn,   0, nullptr, 0);
    jl.j[2] = mkjob(x, 2, Ue,   0, nullptr, 0);
    jl.j[3] = mkjob(x, 3, Ve,   0, nullptr, 0);
    mma_gemm<<<gg, gb, GEMM_SMEM>>>(jl, N);

    // --- edge phase: ONE fused launch, ne-blocks + struct-blocks co-resident ---
    int gNE = (E + 15) / 16;
    int gST = (E + 31) / 32;
    edge_fused<<<gNE + gST, 256>>>(ei, bt, conv_w, conv_b, b_el, coords,
                                   (const float4*)x,
                                   (const float4*)Un, (const float4*)Vn,
                                   (const float4*)Ue, (const float4*)Ve,
                                   (float4*)Pn, (float4*)Pe, (float4*)T,
                                   sArr, dArr, E, gNE);

    // --- L2+L3 merged (all row deps are CTA-local):
    //     Fn, Fe, Qp(chain)->Q(chain)->Fs, per-path HR chains -> E_f,
    //     fused-attention Hagg + BN stats ---
    jl.count = 12;
    jl.j[0]  = mkjob(Pn, 6, Fn, 1, b_nout, 1);
    jl.j[1]  = mkjob(Pe, 7, Fe, 1, b_eout, 1);
    jl.j[2]  = mkjob(x, 8, nullptr, 0, b_coord, 1, T, 9, sArr, dArr, nullptr, 1);
    jl.j[3]  = mkjob(nullptr, 10, nullptr, 1, b_pair, 0, nullptr, -1, nullptr, nullptr, nullptr, 1);
    jl.j[4]  = mkjob(x, 12, Fs, 1, b_sout, 0, x, 11);
    jl.j[5]  = mkjob(Fn, 13, nullptr, 2, nullptr, 1, nullptr, -1, nullptr, nullptr, nullptr, 1);
    jl.j[6]  = mkjob(x, 16, E0, 0, nullptr, 0);
    jl.j[7]  = mkjob(Fe, 14, nullptr, 2, nullptr, 1, nullptr, -1, nullptr, nullptr, nullptr, 1);
    jl.j[8]  = mkjob(x, 16, E1, 0, nullptr, 0);
    jl.j[9]  = mkjob(Fs, 15, nullptr, 2, nullptr, 1, nullptr, -1, nullptr, nullptr, nullptr, 1);
    jl.j[10] = mkjob(x, 16, E2, 0, nullptr, 0);
    jl.j[11] = mkjob(E0, 17, Hagg, 0);
    jl.j[11].attn = 1; jl.j[11].bnstat = 1;
    jl.j[11].aE1 = E1; jl.j[11].aE2 = E2;
    jl.j[11].aF0 = Fn; jl.j[11].aF1 = Fe; jl.j[11].aF2 = Fs;
    mma_gemm<<<gg, gb, GEMM_SMEM>>>(jl, N);

    final_kernel<<<(N * 32 + 255) / 256, 256>>>(
        (const float4*)Hagg, (const float4*)bnS, (const float4*)bnQ,
        (const float4*)gamma, (const float4*)beta, (float4*)d_out, N);
}